// round 10
// baseline (speedup 1.0000x reference)
#include <cuda_runtime.h>
#include <cuda_bf16.h>
#include <math.h>
#include <stdint.h>

// ---------------- problem constants ----------------
#define NODES   20000
#define EDGES   200000
#define DIMC    256
#define HEADS   4
#define DH      64
#define INNER   256
#define EDIM    512
#define FFDIM   1024
#define OUTC    128
#define DEPTH   2

// ---------------- scratch (device globals; no allocation allowed) ----------
__device__ float g_xbuf[NODES * DIMC];
__device__ float g_xn  [NODES * DIMC];
__device__ float g_q   [NODES * DIMC];
__device__ float g_kv  [NODES * 2 * DIMC];
__device__ float g_e   [(size_t)EDGES * DIMC];
__device__ float g_sim [(size_t)EDGES * HEADS];
__device__ float g_agg [NODES * DIMC];
__device__ float g_y   [NODES * DIMC];
__device__ float g_ff  [NODES * FFDIM];
__device__ int   g_counts [NODES];
__device__ int   g_offsets[NODES + 1];
__device__ int   g_cursor [NODES];
__device__ int   g_perm   [EDGES];

// bf16 split buffers (hi/lo)
__device__ __nv_bfloat16 g_act_h[(size_t)NODES * FFDIM];
__device__ __nv_bfloat16 g_act_l[(size_t)NODES * FFDIM];
__device__ __nv_bfloat16 g_ea_h [(size_t)EDGES * EDIM];
__device__ __nv_bfloat16 g_ea_l [(size_t)EDGES * EDIM];

// transposed split weights, [N,K] bf16, per-layer packed
#define WOFF_Q   0
#define WOFF_KV  65536
#define WOFF_E   196608
#define WOFF_O   327680
#define WOFF_F1  393216
#define WOFF_F2  655360
#define WLAYER   917504
#define WOFF_P   (2 * WLAYER)
#define WTOT     (WOFF_P + 32768)
__device__ __nv_bfloat16 g_wh[WTOT];
__device__ __nv_bfloat16 g_wl[WTOT];

__device__ __forceinline__ uint32_t smem_to_u32(const void* p) {
    uint32_t a;
    asm("{ .reg .u64 t; cvta.to.shared.u64 t, %1; cvt.u32.u64 %0, t; }" : "=r"(a) : "l"(p));
    return a;
}

// ---------------- small utility kernels ----------------
__global__ void copy_kernel(const float* __restrict__ src, float* __restrict__ dst, int n) {
    int i = blockIdx.x * blockDim.x + threadIdx.x;
    if (i < n) dst[i] = src[i];
}

__global__ void zero_counts_kernel() {
    int i = blockIdx.x * blockDim.x + threadIdx.x;
    if (i < NODES) g_counts[i] = 0;
}

__global__ void count_kernel(const int* __restrict__ dst) {
    int e = blockIdx.x * blockDim.x + threadIdx.x;
    if (e < EDGES) atomicAdd(&g_counts[dst[e]], 1);
}

// single-block exclusive scan, warp-scan based (1024 threads)
__global__ void scan_kernel() {
    __shared__ int wsum[32];
    const int CHUNK = 20;
    int tid = threadIdx.x, lane = tid & 31, wid = tid >> 5;
    int base = tid * CHUNK;
    int s = 0;
    #pragma unroll
    for (int i = 0; i < CHUNK; i++) {
        int idx = base + i;
        s += (idx < NODES) ? g_counts[idx] : 0;
    }
    int inc = s;
    #pragma unroll
    for (int o = 1; o < 32; o <<= 1) {
        int t = __shfl_up_sync(0xffffffff, inc, o);
        if (lane >= o) inc += t;
    }
    if (lane == 31) wsum[wid] = inc;
    __syncthreads();
    if (wid == 0) {
        int v = wsum[lane];
        int inc2 = v;
        #pragma unroll
        for (int o = 1; o < 32; o <<= 1) {
            int t = __shfl_up_sync(0xffffffff, inc2, o);
            if (lane >= o) inc2 += t;
        }
        wsum[lane] = inc2 - v;
    }
    __syncthreads();
    int run = wsum[wid] + (inc - s);
    #pragma unroll
    for (int i = 0; i < CHUNK; i++) {
        int idx = base + i;
        if (idx <= NODES) g_offsets[idx] = run;
        run += (idx < NODES) ? g_counts[idx] : 0;
    }
}

__global__ void cursor_init_kernel() {
    int i = blockIdx.x * blockDim.x + threadIdx.x;
    if (i < NODES) g_cursor[i] = g_offsets[i];
}

__global__ void scatter_kernel(const int* __restrict__ dst) {
    int e = blockIdx.x * blockDim.x + threadIdx.x;
    if (e < EDGES) {
        int pos = atomicAdd(&g_cursor[dst[e]], 1);
        g_perm[pos] = e;
    }
}

// ---------------- bf16 split (hi + lo) elementwise ----------
__global__ void split_kernel(const float* __restrict__ x, __nv_bfloat16* __restrict__ h,
                             __nv_bfloat16* __restrict__ l, int n4) {
    int i = blockIdx.x * blockDim.x + threadIdx.x;
    if (i >= n4) return;
    float4 v = ((const float4*)x)[i];
    float vv[4] = {v.x, v.y, v.z, v.w};
    uint16_t hs[4], ls[4];
    #pragma unroll
    for (int j = 0; j < 4; j++) {
        __nv_bfloat16 hb = __float2bfloat16(vv[j]);
        __nv_bfloat16 lb = __float2bfloat16(vv[j] - __bfloat162float(hb));
        hs[j] = __bfloat16_as_ushort(hb);
        ls[j] = __bfloat16_as_ushort(lb);
    }
    ((uint2*)h)[i] = make_uint2((uint32_t)hs[0] | ((uint32_t)hs[1] << 16),
                                (uint32_t)hs[2] | ((uint32_t)hs[3] << 16));
    ((uint2*)l)[i] = make_uint2((uint32_t)ls[0] | ((uint32_t)ls[1] << 16),
                                (uint32_t)ls[2] | ((uint32_t)ls[3] << 16));
}

// ---------------- weight transpose + split: [K,N] fp32 -> [N,K] bf16 hi/lo --
__global__ void tsplit_kernel(const float* __restrict__ W, __nv_bfloat16* __restrict__ Th,
                              __nv_bfloat16* __restrict__ Tl, int K, int N) {
    __shared__ float t[32][33];
    int kb = blockIdx.y << 5, nb = blockIdx.x << 5;
    int tx = threadIdx.x, ty = threadIdx.y;  // 32 x 8
    #pragma unroll
    for (int i = 0; i < 32; i += 8)
        t[ty + i][tx] = W[(size_t)(kb + ty + i) * N + nb + tx];
    __syncthreads();
    #pragma unroll
    for (int i = 0; i < 32; i += 8) {
        int n = nb + ty + i, k = kb + tx;
        float v = t[tx][ty + i];
        __nv_bfloat16 hb = __float2bfloat16(v);
        Th[(size_t)n * K + k] = hb;
        Tl[(size_t)n * K + k] = __float2bfloat16(v - __bfloat162float(hb));
    }
}

// ---------------- LayerNorm: warp per row ----------------
__global__ void ln_kernel(const float* __restrict__ x, const float* __restrict__ g,
                          const float* __restrict__ b, float* __restrict__ out) {
    int row = blockIdx.x * (blockDim.x >> 5) + (threadIdx.x >> 5);
    if (row >= NODES) return;
    int lane = threadIdx.x & 31;
    const float* xr = x + (size_t)row * DIMC;
    float vals[8];
    float4 v0 = *(const float4*)(xr + lane * 8);
    float4 v1 = *(const float4*)(xr + lane * 8 + 4);
    vals[0]=v0.x; vals[1]=v0.y; vals[2]=v0.z; vals[3]=v0.w;
    vals[4]=v1.x; vals[5]=v1.y; vals[6]=v1.z; vals[7]=v1.w;
    float s = 0.f, ss = 0.f;
    #pragma unroll
    for (int i = 0; i < 8; i++) { s += vals[i]; ss += vals[i] * vals[i]; }
    #pragma unroll
    for (int o = 16; o > 0; o >>= 1) {
        s  += __shfl_xor_sync(0xffffffff, s,  o);
        ss += __shfl_xor_sync(0xffffffff, ss, o);
    }
    float mean = s * (1.0f / DIMC);
    float var  = ss * (1.0f / DIMC) - mean * mean;
    float rstd = rsqrtf(var + 1e-5f);
    float* orow = out + (size_t)row * DIMC;
    #pragma unroll
    for (int i = 0; i < 8; i++) {
        int c = lane * 8 + i;
        orow[c] = (vals[i] - mean) * rstd * g[c] + b[c];
    }
}

// ---------------- gated residual: warp per row ----------------
__global__ void gated_residual_kernel(const float* __restrict__ y, float* __restrict__ res,
                                      const float* __restrict__ gw) {
    int row = blockIdx.x * (blockDim.x >> 5) + (threadIdx.x >> 5);
    if (row >= NODES) return;
    int lane = threadIdx.x & 31;
    const float* yr = y   + (size_t)row * DIMC;
    float*       rr = res + (size_t)row * DIMC;
    float yv[8], rv[8];
    float z = 0.f;
    #pragma unroll
    for (int i = 0; i < 8; i++) {
        int c = lane * 8 + i;
        yv[i] = yr[c];
        rv[i] = rr[c];
        float w1 = gw[c], w2 = gw[DIMC + c], w3 = gw[2 * DIMC + c];
        z += yv[i] * (w1 + w3) + rv[i] * (w2 - w3);
    }
    #pragma unroll
    for (int o = 16; o > 0; o >>= 1) z += __shfl_xor_sync(0xffffffff, z, o);
    float gate = 1.0f / (1.0f + __expf(-z));
    #pragma unroll
    for (int i = 0; i < 8; i++) {
        int c = lane * 8 + i;
        rr[c] = yv[i] * gate + rv[i] * (1.0f - gate);
    }
}

// ================= HMMA GEMM: C[M,N] = A @ B^T (3-term bf16 split) =========
// A_hi/A_lo: [M,K] bf16 row-major.  B_hi/B_lo: [N,K] bf16 row-major.
// CTA tile 128x64, K-chunk 32, 8 warps of 32x32, mma.m16n8k16, cp.async x2.
// 2 CTAs per SM (61.4 KB smem each) to fill pipeline bubbles.
__device__ __forceinline__ float gelu_f(float v) {
    float c = 0.7978845608028654f * (v + 0.044715f * v * v * v);
    return 0.5f * v * (1.0f + tanhf(c));
}

#define STRB 80                       // smem bytes per 32-col bf16 row (64B + 16 pad)
#define ATILEB (128 * STRB)           // 10240 B
#define BTILEB (64 * STRB)            // 5120 B
#define OFF_AH 0
#define OFF_AL ATILEB
#define OFF_BH (2 * ATILEB)
#define OFF_BL (2 * ATILEB + BTILEB)
#define STAGEB (2 * ATILEB + 2 * BTILEB)   // 30720 B
#define GEMM_SMEM (2 * STAGEB)             // 61440 B

__device__ __forceinline__ void cp_async16z(uint32_t dst, const void* src, int sz) {
    asm volatile("cp.async.cg.shared.global [%0], [%1], 16, %2;"
                 :: "r"(dst), "l"(src), "r"(sz));
}
__device__ __forceinline__ void cp_async16(uint32_t dst, const void* src) {
    asm volatile("cp.async.cg.shared.global [%0], [%1], 16;" :: "r"(dst), "l"(src));
}
__device__ __forceinline__ void ldm_x4(uint32_t* r, uint32_t addr) {
    asm volatile("ldmatrix.sync.aligned.m8n8.x4.shared.b16 {%0,%1,%2,%3}, [%4];"
                 : "=r"(r[0]), "=r"(r[1]), "=r"(r[2]), "=r"(r[3]) : "r"(addr));
}
__device__ __forceinline__ void ldm_x2(uint32_t* r, uint32_t addr) {
    asm volatile("ldmatrix.sync.aligned.m8n8.x2.shared.b16 {%0,%1}, [%2];"
                 : "=r"(r[0]), "=r"(r[1]) : "r"(addr));
}
__device__ __forceinline__ void mma_bf16(float* d, const uint32_t* a, const uint32_t* b) {
    asm volatile("mma.sync.aligned.m16n8k16.row.col.f32.bf16.bf16.f32 "
                 "{%0,%1,%2,%3}, {%4,%5,%6,%7}, {%8,%9}, {%0,%1,%2,%3};"
                 : "+f"(d[0]), "+f"(d[1]), "+f"(d[2]), "+f"(d[3])
                 : "r"(a[0]), "r"(a[1]), "r"(a[2]), "r"(a[3]), "r"(b[0]), "r"(b[1]));
}

template<int EPI>
__global__ __launch_bounds__(256, 2) void gemm_mma(
        const __nv_bfloat16* __restrict__ Ah, const __nv_bfloat16* __restrict__ Al,
        const __nv_bfloat16* __restrict__ Bh, const __nv_bfloat16* __restrict__ Bl,
        const float* __restrict__ bias, float* __restrict__ C, int M, int N, int K) {
    extern __shared__ char smem[];
    uint32_t sb = smem_to_u32(smem);
    int tid = threadIdx.x, wid = tid >> 5, lane = tid & 31;
    int bm = blockIdx.y * 128, bn = blockIdx.x * 64;
    int wm = (wid & 3) * 32, wn = (wid >> 2) * 32;

    float acc[2][4][4];
    #pragma unroll
    for (int i = 0; i < 2; i++)
        #pragma unroll
        for (int j = 0; j < 4; j++)
            #pragma unroll
            for (int k = 0; k < 4; k++) acc[i][j][k] = 0.f;

    int row_ld = tid >> 2;          // 0..63
    int seg    = tid & 3;           // 16B segment within 64B row
    int nch = K >> 5;

    // loader: chunk c into stage s
    auto load_chunk = [&](int c, int s) {
        int k0 = c << 5;
        uint32_t base = sb + s * STAGEB;
        // A: rows row_ld and row_ld+64 (hi + lo)
        #pragma unroll
        for (int it = 0; it < 2; it++) {
            int row = row_ld + it * 64;
            uint32_t doff = row * STRB + seg * 16;
            int gm = bm + row;
            int sz = (gm < M) ? 16 : 0;
            int gmc = (gm < M) ? gm : (M - 1);
            const char* pa = (const char*)(Ah + (size_t)gmc * K + k0) + seg * 16;
            const char* pl = (const char*)(Al + (size_t)gmc * K + k0) + seg * 16;
            cp_async16z(base + OFF_AH + doff, pa, sz);
            cp_async16z(base + OFF_AL + doff, pl, sz);
        }
        // B: row row_ld (hi + lo), 64 rows
        {
            uint32_t doff = row_ld * STRB + seg * 16;
            int gn = bn + row_ld;
            const char* pb = (const char*)(Bh + (size_t)gn * K + k0) + seg * 16;
            const char* pc = (const char*)(Bl + (size_t)gn * K + k0) + seg * 16;
            cp_async16(base + OFF_BH + doff, pb);
            cp_async16(base + OFF_BL + doff, pc);
        }
    };

    load_chunk(0, 0);
    asm volatile("cp.async.commit_group;");

    int a_row = lane & 15;
    int a_col = (lane >> 4) * 16;
    int b_row = lane & 7;
    int b_col = ((lane >> 3) & 1) * 16;

    for (int c = 0; c < nch; c++) {
        if (c + 1 < nch) {
            load_chunk(c + 1, (c + 1) & 1);
            asm volatile("cp.async.commit_group;");
            asm volatile("cp.async.wait_group 1;");
        } else {
            asm volatile("cp.async.wait_group 0;");
        }
        __syncthreads();

        uint32_t stg = sb + (c & 1) * STAGEB;
        uint32_t sah = stg + OFF_AH;
        uint32_t sal = stg + OFF_AL;
        uint32_t sbh = stg + OFF_BH;
        uint32_t sbl = stg + OFF_BL;

        #pragma unroll
        for (int kk = 0; kk < 2; kk++) {
            uint32_t ah[2][4], al[2][4], bh[4][2], bl[4][2];
            #pragma unroll
            for (int mt = 0; mt < 2; mt++) {
                uint32_t ra = (wm + mt * 16 + a_row) * STRB + kk * 32 + a_col;
                ldm_x4(ah[mt], sah + ra);
                ldm_x4(al[mt], sal + ra);
            }
            #pragma unroll
            for (int nt = 0; nt < 4; nt++) {
                uint32_t rb = (wn + nt * 8 + b_row) * STRB + kk * 32 + b_col;
                ldm_x2(bh[nt], sbh + rb);
                ldm_x2(bl[nt], sbl + rb);
            }
            #pragma unroll
            for (int mt = 0; mt < 2; mt++)
                #pragma unroll
                for (int nt = 0; nt < 4; nt++) {
                    mma_bf16(acc[mt][nt], ah[mt], bh[nt]);
                    mma_bf16(acc[mt][nt], ah[mt], bl[nt]);
                    mma_bf16(acc[mt][nt], al[mt], bh[nt]);
                }
        }
        __syncthreads();
    }

    // epilogue: d0,d1 -> (m, n..n+1); d2,d3 -> (m+8, n..n+1)
    int qm = lane >> 2, qn = 2 * (lane & 3);
    #pragma unroll
    for (int mt = 0; mt < 2; mt++) {
        #pragma unroll
        for (int nt = 0; nt < 4; nt++) {
            int m0 = bm + wm + mt * 16 + qm;
            int n0 = bn + wn + nt * 8 + qn;
            float b0 = bias[n0], b1 = bias[n0 + 1];
            #pragma unroll
            for (int half = 0; half < 2; half++) {
                int m = m0 + half * 8;
                if (m < M) {
                    float v0 = acc[mt][nt][half * 2 + 0] + b0;
                    float v1 = acc[mt][nt][half * 2 + 1] + b1;
                    if (EPI == 1) { v0 = gelu_f(v0); v1 = gelu_f(v1); }
                    *(float2*)(C + (size_t)m * N + n0) = make_float2(v0, v1);
                }
            }
        }
    }
}

// ---------------- attention: one block (128 thr) per destination node -------
__global__ void attn_kernel(const int* __restrict__ src) {
    __shared__ float qs[DIMC];
    __shared__ float wm[4][4], wd[4][4];
    __shared__ float fm[4], fd[4];

    int node = blockIdx.x;
    int tid = threadIdx.x;
    int warp = tid >> 5, lane = tid & 31;
    int rs  = g_offsets[node];
    int deg = g_offsets[node + 1] - rs;

    if (deg == 0) {
        g_agg[(size_t)node * DIMC + tid]       = 0.f;
        g_agg[(size_t)node * DIMC + 128 + tid] = 0.f;
        return;
    }

    qs[tid]       = g_q[(size_t)node * DIMC + tid];
    qs[tid + 128] = g_q[(size_t)node * DIMC + 128 + tid];
    __syncthreads();

    float m[4] = {-1e30f, -1e30f, -1e30f, -1e30f};
    float den[4] = {0.f, 0.f, 0.f, 0.f};
    for (int j = warp; j < deg; j += 4) {
        int eid = g_perm[rs + j];
        int s = src[eid];
        const float* kp = g_kv + (size_t)s * (2 * DIMC);
        const float* ep = g_e  + (size_t)eid * DIMC;
        float sh[4];
        #pragma unroll
        for (int h = 0; h < 4; h++) {
            int c = h * 64 + lane * 2;
            float2 kf = *(const float2*)(kp + c);
            float2 ef = *(const float2*)(ep + c);
            float2 qf = *(const float2*)(qs + c);
            sh[h] = (kf.x + ef.x) * qf.x + (kf.y + ef.y) * qf.y;
        }
        #pragma unroll
        for (int h = 0; h < 4; h++) {
            float v = sh[h];
            #pragma unroll
            for (int o = 16; o > 0; o >>= 1) v += __shfl_xor_sync(0xffffffff, v, o);
            sh[h] = v * 0.125f;
        }
        if (lane == 0) {
            *(float4*)(g_sim + (size_t)(rs + j) * 4) = make_float4(sh[0], sh[1], sh[2], sh[3]);
        }
        #pragma unroll
        for (int h = 0; h < 4; h++) {
            float mn = fmaxf(m[h], sh[h]);
            den[h] = den[h] * __expf(m[h] - mn) + __expf(sh[h] - mn);
            m[h] = mn;
        }
    }
    if (lane == 0) {
        #pragma unroll
        for (int h = 0; h < 4; h++) { wm[warp][h] = m[h]; wd[warp][h] = den[h]; }
    }
    __syncthreads();
    if (tid < 4) {
        int h = tid;
        float M_ = -1e30f;
        #pragma unroll
        for (int w = 0; w < 4; w++) M_ = fmaxf(M_, wm[w][h]);
        float D = 0.f;
        #pragma unroll
        for (int w = 0; w < 4; w++) D += wd[w][h] * __expf(wm[w][h] - M_);
        fm[h] = M_;
        fd[h] = D;
    }
    __syncthreads();

    int c0 = tid, c1 = tid + 128;
    int h0 = c0 >> 6, h1 = c1 >> 6;
    float rm0 = fm[h0], rm1 = fm[h1];
    float rd0 = 1.0f / fd[h0], rd1 = 1.0f / fd[h1];
    float acc0 = 0.f, acc1 = 0.f;
    for (int j = 0; j < deg; j++) {
        int eid = g_perm[rs + j];
        int s = src[eid];
        float p0 = __expf(g_sim[(size_t)(rs + j) * 4 + h0] - rm0) * rd0;
        float p1 = __expf(g_sim[(size_t)(rs + j) * 4 + h1] - rm1) * rd1;
        const float* vp = g_kv + (size_t)s * (2 * DIMC) + DIMC;
        const float* ep = g_e  + (size_t)eid * DIMC;
        acc0 += p0 * (vp[c0] + ep[c0]);
        acc1 += p1 * (vp[c1] + ep[c1]);
    }
    g_agg[(size_t)node * DIMC + c0] = acc0;
    g_agg[(size_t)node * DIMC + c1] = acc1;
}

// ---------------- host orchestration ----------------
static inline dim3 tc_grid(int M, int N) {
    return dim3(N / 64, (M + 127) / 128);
}

extern "C" void kernel_launch(void* const* d_in, const int* in_sizes, int n_in,
                              void* d_out, int out_size) {
    const float* x         = (const float*)d_in[0];
    const float* edge_attr = (const float*)d_in[1];
    const int*   edge_idx  = (const int*)  d_in[2];
    const float* ln1_g     = (const float*)d_in[3];
    const float* ln1_b     = (const float*)d_in[4];
    const float* Wq        = (const float*)d_in[5];
    const float* bq        = (const float*)d_in[6];
    const float* Wkv       = (const float*)d_in[7];
    const float* bkv       = (const float*)d_in[8];
    const float* We        = (const float*)d_in[9];
    const float* be        = (const float*)d_in[10];
    const float* Wo        = (const float*)d_in[11];
    const float* bo        = (const float*)d_in[12];
    const float* gate_attn = (const float*)d_in[13];
    const float* ln2_g     = (const float*)d_in[14];
    const float* ln2_b     = (const float*)d_in[15];
    const float* Wff1      = (const float*)d_in[16];
    const float* bff1      = (const float*)d_in[17];
    const float* Wff2      = (const float*)d_in[18];
    const float* bff2      = (const float*)d_in[19];
    const float* gate_ff   = (const float*)d_in[20];
    const float* Wproj     = (const float*)d_in[21];
    const float* bproj     = (const float*)d_in[22];

    const int* src_arr = edge_idx;
    const int* dst_arr = edge_idx + EDGES;

    cudaFuncSetAttribute(gemm_mma<0>, cudaFuncAttributeMaxDynamicSharedMemorySize, GEMM_SMEM);
    cudaFuncSetAttribute(gemm_mma<1>, cudaFuncAttributeMaxDynamicSharedMemorySize, GEMM_SMEM);

    float *p_xbuf, *p_xn, *p_q, *p_kv, *p_e, *p_agg, *p_y, *p_ff;
    __nv_bfloat16 *p_ah, *p_al, *p_eah, *p_eal, *p_wh, *p_wl;
    cudaGetSymbolAddress((void**)&p_xbuf, g_xbuf);
    cudaGetSymbolAddress((void**)&p_xn,   g_xn);
    cudaGetSymbolAddress((void**)&p_q,    g_q);
    cudaGetSymbolAddress((void**)&p_kv,   g_kv);
    cudaGetSymbolAddress((void**)&p_e,    g_e);
    cudaGetSymbolAddress((void**)&p_agg,  g_agg);
    cudaGetSymbolAddress((void**)&p_y,    g_y);
    cudaGetSymbolAddress((void**)&p_ff,   g_ff);
    cudaGetSymbolAddress((void**)&p_ah,   g_act_h);
    cudaGetSymbolAddress((void**)&p_al,   g_act_l);
    cudaGetSymbolAddress((void**)&p_eah,  g_ea_h);
    cudaGetSymbolAddress((void**)&p_eal,  g_ea_l);
    cudaGetSymbolAddress((void**)&p_wh,   g_wh);
    cudaGetSymbolAddress((void**)&p_wl,   g_wl);

    // residual init
    copy_kernel<<<(NODES * DIMC + 255) / 256, 256>>>(x, p_xbuf, NODES * DIMC);

    // CSR of incoming edges
    zero_counts_kernel<<<(NODES + 255) / 256, 256>>>();
    count_kernel<<<(EDGES + 255) / 256, 256>>>(dst_arr);
    scan_kernel<<<1, 1024>>>();
    cursor_init_kernel<<<(NODES + 255) / 256, 256>>>();
    scatter_kernel<<<(EDGES + 255) / 256, 256>>>(dst_arr);

    // weight transpose + split (once per launch)
    dim3 tb(32, 8);
    for (int d = 0; d < DEPTH; d++) {
        size_t wb = (size_t)d * WLAYER;
        tsplit_kernel<<<dim3(INNER/32,  DIMC/32),  tb>>>(Wq   + (size_t)d*DIMC*INNER,    p_wh + wb + WOFF_Q,  p_wl + wb + WOFF_Q,  DIMC,  INNER);
        tsplit_kernel<<<dim3(2*INNER/32,DIMC/32),  tb>>>(Wkv  + (size_t)d*DIMC*2*INNER,  p_wh + wb + WOFF_KV, p_wl + wb + WOFF_KV, DIMC,  2*INNER);
        tsplit_kernel<<<dim3(INNER/32,  EDIM/32),  tb>>>(We   + (size_t)d*EDIM*INNER,    p_wh + wb + WOFF_E,  p_wl + wb + WOFF_E,  EDIM,  INNER);
        tsplit_kernel<<<dim3(DIMC/32,   INNER/32), tb>>>(Wo   + (size_t)d*INNER*DIMC,    p_wh + wb + WOFF_O,  p_wl + wb + WOFF_O,  INNER, DIMC);
        tsplit_kernel<<<dim3(FFDIM/32,  DIMC/32),  tb>>>(Wff1 + (size_t)d*DIMC*FFDIM,    p_wh + wb + WOFF_F1, p_wl + wb + WOFF_F1, DIMC,  FFDIM);
        tsplit_kernel<<<dim3(DIMC/32,   FFDIM/32), tb>>>(Wff2 + (size_t)d*FFDIM*DIMC,    p_wh + wb + WOFF_F2, p_wl + wb + WOFF_F2, FFDIM, DIMC);
    }
    tsplit_kernel<<<dim3(OUTC/32, DIMC/32), tb>>>(Wproj, p_wh + WOFF_P, p_wl + WOFF_P, DIMC, OUTC);

    // edge features split (once; reused both layers)
    {
        int n4 = EDGES * EDIM / 4;
        split_kernel<<<(n4 + 255) / 256, 256>>>(edge_attr, p_eah, p_eal, n4);
    }

    int warps_rows_blocks = (NODES + 7) / 8;
    int n4_xn = NODES * DIMC / 4;
    int n4_ff = NODES * FFDIM / 4;

    for (int d = 0; d < DEPTH; d++) {
        size_t wb = (size_t)d * WLAYER;
        // pre-norm + split
        ln_kernel<<<warps_rows_blocks, 256>>>(p_xbuf, ln1_g + d * DIMC, ln1_b + d * DIMC, p_xn);
        split_kernel<<<(n4_xn + 255) / 256, 256>>>(p_xn, p_ah, p_al, n4_xn);
        // projections (tensor cores)
        gemm_mma<0><<<tc_grid(NODES, INNER), 256, GEMM_SMEM>>>(
            p_ah, p_al, p_wh + wb + WOFF_Q, p_wl + wb + WOFF_Q, bq + d * INNER, p_q, NODES, INNER, DIMC);
        gemm_mma<0><<<tc_grid(NODES, 2 * INNER), 256, GEMM_SMEM>>>(
            p_ah, p_al, p_wh + wb + WOFF_KV, p_wl + wb + WOFF_KV, bkv + d * 2 * INNER, p_kv, NODES, 2 * INNER, DIMC);
        gemm_mma<0><<<tc_grid(EDGES, INNER), 256, GEMM_SMEM>>>(
            p_eah, p_eal, p_wh + wb + WOFF_E, p_wl + wb + WOFF_E, be + d * INNER, p_e, EDGES, INNER, EDIM);
        // sparse attention
        attn_kernel<<<NODES, 128>>>(src_arr);
        // output projection + gated residual
        split_kernel<<<(n4_xn + 255) / 256, 256>>>(p_agg, p_ah, p_al, n4_xn);
        gemm_mma<0><<<tc_grid(NODES, DIMC), 256, GEMM_SMEM>>>(
            p_ah, p_al, p_wh + wb + WOFF_O, p_wl + wb + WOFF_O, bo + d * DIMC, p_y, NODES, DIMC, INNER);
        gated_residual_kernel<<<warps_rows_blocks, 256>>>(p_y, p_xbuf, gate_attn + (size_t)d * 3 * DIMC);
        // feedforward
        ln_kernel<<<warps_rows_blocks, 256>>>(p_xbuf, ln2_g + d * DIMC, ln2_b + d * DIMC, p_xn);
        split_kernel<<<(n4_xn + 255) / 256, 256>>>(p_xn, p_ah, p_al, n4_xn);
        gemm_mma<1><<<tc_grid(NODES, FFDIM), 256, GEMM_SMEM>>>(
            p_ah, p_al, p_wh + wb + WOFF_F1, p_wl + wb + WOFF_F1, bff1 + d * FFDIM, p_ff, NODES, FFDIM, DIMC);
        split_kernel<<<(n4_ff + 255) / 256, 256>>>(p_ff, p_ah, p_al, n4_ff);
        gemm_mma<0><<<tc_grid(NODES, DIMC), 256, GEMM_SMEM>>>(
            p_ah, p_al, p_wh + wb + WOFF_F2, p_wl + wb + WOFF_F2, bff2 + d * DIMC, p_y, NODES, DIMC, FFDIM);
        gated_residual_kernel<<<warps_rows_blocks, 256>>>(p_y, p_xbuf, gate_ff + (size_t)d * 3 * DIMC);
    }

    // final projection
    split_kernel<<<(n4_xn + 255) / 256, 256>>>(p_xbuf, p_ah, p_al, n4_xn);
    gemm_mma<0><<<tc_grid(NODES, OUTC), 256, GEMM_SMEM>>>(
        p_ah, p_al, p_wh + WOFF_P, p_wl + WOFF_P, bproj, (float*)d_out, NODES, OUTC, DIMC);
}

// round 12
// speedup vs baseline: 1.3658x; 1.3658x over previous
#include <cuda_runtime.h>
#include <cuda_bf16.h>
#include <math.h>
#include <stdint.h>

// ---------------- problem constants ----------------
#define NODES   20000
#define EDGES   200000
#define DIMC    256
#define HEADS   4
#define DH      64
#define INNER   256
#define EDIM    512
#define FFDIM   1024
#define OUTC    128
#define DEPTH   2

// ---------------- scratch (device globals; no allocation allowed) ----------
__device__ float g_xbuf[NODES * DIMC];
__device__ float g_xn  [NODES * DIMC];
__device__ float g_q   [NODES * DIMC];
__device__ float g_kv  [NODES * 2 * DIMC];
__device__ float g_e   [(size_t)DEPTH * EDGES * DIMC];   // both layers precomputed
__device__ float g_sim [(size_t)EDGES * HEADS];
__device__ float g_agg [NODES * DIMC];
__device__ float g_y   [NODES * DIMC];
__device__ float g_ff  [NODES * FFDIM];
__device__ int   g_counts [NODES];
__device__ int   g_offsets[NODES + 1];
__device__ int   g_cursor [NODES];
__device__ int   g_perm   [EDGES];

// bf16 split buffers (hi/lo)
__device__ __nv_bfloat16 g_act_h[(size_t)NODES * FFDIM];
__device__ __nv_bfloat16 g_act_l[(size_t)NODES * FFDIM];
__device__ __nv_bfloat16 g_ea_h [(size_t)EDGES * EDIM];
__device__ __nv_bfloat16 g_ea_l [(size_t)EDGES * EDIM];

// transposed split weights, [N,K] bf16, per-layer packed
#define WOFF_Q   0
#define WOFF_KV  65536
#define WOFF_E   196608
#define WOFF_O   327680
#define WOFF_F1  393216
#define WOFF_F2  655360
#define WLAYER   917504
#define WOFF_P   (2 * WLAYER)
#define WTOT     (WOFF_P + 32768)
__device__ __nv_bfloat16 g_wh[WTOT];
__device__ __nv_bfloat16 g_wl[WTOT];

__device__ __forceinline__ uint32_t smem_to_u32(const void* p) {
    uint32_t a;
    asm("{ .reg .u64 t; cvta.to.shared.u64 t, %1; cvt.u32.u64 %0, t; }" : "=r"(a) : "l"(p));
    return a;
}

// ---------------- small utility kernels ----------------
__global__ void copy_kernel(const float* __restrict__ src, float* __restrict__ dst, int n) {
    int i = blockIdx.x * blockDim.x + threadIdx.x;
    if (i < n) dst[i] = src[i];
}

__global__ void zero_counts_kernel() {
    int i = blockIdx.x * blockDim.x + threadIdx.x;
    if (i < NODES) g_counts[i] = 0;
}

__global__ void count_kernel(const int* __restrict__ dst) {
    int e = blockIdx.x * blockDim.x + threadIdx.x;
    if (e < EDGES) atomicAdd(&g_counts[dst[e]], 1);
}

// single-block exclusive scan, warp-scan based (1024 threads)
__global__ void scan_kernel() {
    __shared__ int wsum[32];
    const int CHUNK = 20;
    int tid = threadIdx.x, lane = tid & 31, wid = tid >> 5;
    int base = tid * CHUNK;
    int s = 0;
    #pragma unroll
    for (int i = 0; i < CHUNK; i++) {
        int idx = base + i;
        s += (idx < NODES) ? g_counts[idx] : 0;
    }
    int inc = s;
    #pragma unroll
    for (int o = 1; o < 32; o <<= 1) {
        int t = __shfl_up_sync(0xffffffff, inc, o);
        if (lane >= o) inc += t;
    }
    if (lane == 31) wsum[wid] = inc;
    __syncthreads();
    if (wid == 0) {
        int v = wsum[lane];
        int inc2 = v;
        #pragma unroll
        for (int o = 1; o < 32; o <<= 1) {
            int t = __shfl_up_sync(0xffffffff, inc2, o);
            if (lane >= o) inc2 += t;
        }
        wsum[lane] = inc2 - v;
    }
    __syncthreads();
    int run = wsum[wid] + (inc - s);
    #pragma unroll
    for (int i = 0; i < CHUNK; i++) {
        int idx = base + i;
        if (idx <= NODES) g_offsets[idx] = run;
        run += (idx < NODES) ? g_counts[idx] : 0;
    }
}

__global__ void cursor_init_kernel() {
    int i = blockIdx.x * blockDim.x + threadIdx.x;
    if (i < NODES) g_cursor[i] = g_offsets[i];
}

__global__ void scatter_kernel(const int* __restrict__ dst) {
    int e = blockIdx.x * blockDim.x + threadIdx.x;
    if (e < EDGES) {
        int pos = atomicAdd(&g_cursor[dst[e]], 1);
        g_perm[pos] = e;
    }
}

// ---------------- bf16 split (hi + lo) elementwise ----------
__global__ void split_kernel(const float* __restrict__ x, __nv_bfloat16* __restrict__ h,
                             __nv_bfloat16* __restrict__ l, int n4) {
    int i = blockIdx.x * blockDim.x + threadIdx.x;
    if (i >= n4) return;
    float4 v = ((const float4*)x)[i];
    float vv[4] = {v.x, v.y, v.z, v.w};
    uint16_t hs[4], ls[4];
    #pragma unroll
    for (int j = 0; j < 4; j++) {
        __nv_bfloat16 hb = __float2bfloat16(vv[j]);
        __nv_bfloat16 lb = __float2bfloat16(vv[j] - __bfloat162float(hb));
        hs[j] = __bfloat16_as_ushort(hb);
        ls[j] = __bfloat16_as_ushort(lb);
    }
    ((uint2*)h)[i] = make_uint2((uint32_t)hs[0] | ((uint32_t)hs[1] << 16),
                                (uint32_t)hs[2] | ((uint32_t)hs[3] << 16));
    ((uint2*)l)[i] = make_uint2((uint32_t)ls[0] | ((uint32_t)ls[1] << 16),
                                (uint32_t)ls[2] | ((uint32_t)ls[3] << 16));
}

// ---------------- weight transpose + split: [K,N] fp32 -> [N,K] bf16 hi/lo --
__global__ void tsplit_kernel(const float* __restrict__ W, __nv_bfloat16* __restrict__ Th,
                              __nv_bfloat16* __restrict__ Tl, int K, int N) {
    __shared__ float t[32][33];
    int kb = blockIdx.y << 5, nb = blockIdx.x << 5;
    int tx = threadIdx.x, ty = threadIdx.y;  // 32 x 8
    #pragma unroll
    for (int i = 0; i < 32; i += 8)
        t[ty + i][tx] = W[(size_t)(kb + ty + i) * N + nb + tx];
    __syncthreads();
    #pragma unroll
    for (int i = 0; i < 32; i += 8) {
        int n = nb + ty + i, k = kb + tx;
        float v = t[tx][ty + i];
        __nv_bfloat16 hb = __float2bfloat16(v);
        Th[(size_t)n * K + k] = hb;
        Tl[(size_t)n * K + k] = __float2bfloat16(v - __bfloat162float(hb));
    }
}

// ---------------- LayerNorm: warp per row ----------------
__global__ void ln_kernel(const float* __restrict__ x, const float* __restrict__ g,
                          const float* __restrict__ b, float* __restrict__ out) {
    int row = blockIdx.x * (blockDim.x >> 5) + (threadIdx.x >> 5);
    if (row >= NODES) return;
    int lane = threadIdx.x & 31;
    const float* xr = x + (size_t)row * DIMC;
    float vals[8];
    float4 v0 = *(const float4*)(xr + lane * 8);
    float4 v1 = *(const float4*)(xr + lane * 8 + 4);
    vals[0]=v0.x; vals[1]=v0.y; vals[2]=v0.z; vals[3]=v0.w;
    vals[4]=v1.x; vals[5]=v1.y; vals[6]=v1.z; vals[7]=v1.w;
    float s = 0.f, ss = 0.f;
    #pragma unroll
    for (int i = 0; i < 8; i++) { s += vals[i]; ss += vals[i] * vals[i]; }
    #pragma unroll
    for (int o = 16; o > 0; o >>= 1) {
        s  += __shfl_xor_sync(0xffffffff, s,  o);
        ss += __shfl_xor_sync(0xffffffff, ss, o);
    }
    float mean = s * (1.0f / DIMC);
    float var  = ss * (1.0f / DIMC) - mean * mean;
    float rstd = rsqrtf(var + 1e-5f);
    float* orow = out + (size_t)row * DIMC;
    #pragma unroll
    for (int i = 0; i < 8; i++) {
        int c = lane * 8 + i;
        orow[c] = (vals[i] - mean) * rstd * g[c] + b[c];
    }
}

// ---------------- gated residual: warp per row ----------------
__global__ void gated_residual_kernel(const float* __restrict__ y, float* __restrict__ res,
                                      const float* __restrict__ gw) {
    int row = blockIdx.x * (blockDim.x >> 5) + (threadIdx.x >> 5);
    if (row >= NODES) return;
    int lane = threadIdx.x & 31;
    const float* yr = y   + (size_t)row * DIMC;
    float*       rr = res + (size_t)row * DIMC;
    float yv[8], rv[8];
    float z = 0.f;
    #pragma unroll
    for (int i = 0; i < 8; i++) {
        int c = lane * 8 + i;
        yv[i] = yr[c];
        rv[i] = rr[c];
        float w1 = gw[c], w2 = gw[DIMC + c], w3 = gw[2 * DIMC + c];
        z += yv[i] * (w1 + w3) + rv[i] * (w2 - w3);
    }
    #pragma unroll
    for (int o = 16; o > 0; o >>= 1) z += __shfl_xor_sync(0xffffffff, z, o);
    float gate = 1.0f / (1.0f + __expf(-z));
    #pragma unroll
    for (int i = 0; i < 8; i++) {
        int c = lane * 8 + i;
        rr[c] = yv[i] * gate + rv[i] * (1.0f - gate);
    }
}

// ---------------- common MMA helpers ----------------
__device__ __forceinline__ float gelu_f(float v) {
    float c = 0.7978845608028654f * (v + 0.044715f * v * v * v);
    return 0.5f * v * (1.0f + tanhf(c));
}
__device__ __forceinline__ void cp_async16z(uint32_t dst, const void* src, int sz) {
    asm volatile("cp.async.cg.shared.global [%0], [%1], 16, %2;"
                 :: "r"(dst), "l"(src), "r"(sz));
}
__device__ __forceinline__ void cp_async16(uint32_t dst, const void* src) {
    asm volatile("cp.async.cg.shared.global [%0], [%1], 16;" :: "r"(dst), "l"(src));
}
__device__ __forceinline__ void ldm_x4(uint32_t* r, uint32_t addr) {
    asm volatile("ldmatrix.sync.aligned.m8n8.x4.shared.b16 {%0,%1,%2,%3}, [%4];"
                 : "=r"(r[0]), "=r"(r[1]), "=r"(r[2]), "=r"(r[3]) : "r"(addr));
}
__device__ __forceinline__ void ldm_x2(uint32_t* r, uint32_t addr) {
    asm volatile("ldmatrix.sync.aligned.m8n8.x2.shared.b16 {%0,%1}, [%2];"
                 : "=r"(r[0]), "=r"(r[1]) : "r"(addr));
}
__device__ __forceinline__ void mma_bf16(float* d, const uint32_t* a, const uint32_t* b) {
    asm volatile("mma.sync.aligned.m16n8k16.row.col.f32.bf16.bf16.f32 "
                 "{%0,%1,%2,%3}, {%4,%5,%6,%7}, {%8,%9}, {%0,%1,%2,%3};"
                 : "+f"(d[0]), "+f"(d[1]), "+f"(d[2]), "+f"(d[3])
                 : "r"(a[0]), "r"(a[1]), "r"(a[2]), "r"(a[3]), "r"(b[0]), "r"(b[1]));
}

#define STRB 80                       // smem bytes per 32-col bf16 row (64B + 16 pad)

// ================= narrow GEMM (R7): CTA tile 128x128, for N % 256 != 0 =====
#define N_TILEB (128 * STRB)            // 10240 B per tile
#define N_STAGEB (4 * N_TILEB)          // Ah, Al, Bh, Bl
#define N_GEMM_SMEM (2 * N_STAGEB)      // 81920 B

template<int EPI>
__global__ __launch_bounds__(256, 1) void gemm_mma(
        const __nv_bfloat16* __restrict__ Ah, const __nv_bfloat16* __restrict__ Al,
        const __nv_bfloat16* __restrict__ Bh, const __nv_bfloat16* __restrict__ Bl,
        const float* __restrict__ bias, float* __restrict__ C, int M, int N, int K) {
    extern __shared__ char smem[];
    uint32_t sb = smem_to_u32(smem);
    int tid = threadIdx.x, wid = tid >> 5, lane = tid & 31;
    int bm = blockIdx.y * 128, bn = blockIdx.x * 128;
    int wm = (wid & 1) * 64, wn = (wid >> 1) * 32;

    float acc[4][4][4];
    #pragma unroll
    for (int i = 0; i < 4; i++)
        #pragma unroll
        for (int j = 0; j < 4; j++)
            #pragma unroll
            for (int k = 0; k < 4; k++) acc[i][j][k] = 0.f;

    int row_ld = tid >> 2;
    int seg    = tid & 3;
    int nch = K >> 5;

    auto load_chunk = [&](int c, int s) {
        int k0 = c << 5;
        uint32_t base = sb + s * N_STAGEB;
        #pragma unroll
        for (int it = 0; it < 2; it++) {
            int row = row_ld + it * 64;
            uint32_t doff = row * STRB + seg * 16;
            int gm = bm + row;
            int sz = (gm < M) ? 16 : 0;
            int gmc = (gm < M) ? gm : (M - 1);
            const char* pa = (const char*)(Ah + (size_t)gmc * K + k0) + seg * 16;
            const char* pl = (const char*)(Al + (size_t)gmc * K + k0) + seg * 16;
            cp_async16z(base + 0 * N_TILEB + doff, pa, sz);
            cp_async16z(base + 1 * N_TILEB + doff, pl, sz);
            int gn = bn + row;
            const char* pb = (const char*)(Bh + (size_t)gn * K + k0) + seg * 16;
            const char* pc = (const char*)(Bl + (size_t)gn * K + k0) + seg * 16;
            cp_async16(base + 2 * N_TILEB + doff, pb);
            cp_async16(base + 3 * N_TILEB + doff, pc);
        }
    };

    load_chunk(0, 0);
    asm volatile("cp.async.commit_group;");

    int a_row = lane & 15;
    int a_col = (lane >> 4) * 16;
    int b_row = lane & 7;
    int b_col = ((lane >> 3) & 1) * 16;

    for (int c = 0; c < nch; c++) {
        if (c + 1 < nch) {
            load_chunk(c + 1, (c + 1) & 1);
            asm volatile("cp.async.commit_group;");
            asm volatile("cp.async.wait_group 1;");
        } else {
            asm volatile("cp.async.wait_group 0;");
        }
        __syncthreads();

        uint32_t stg = sb + (c & 1) * N_STAGEB;
        uint32_t sah = stg + 0 * N_TILEB;
        uint32_t sal = stg + 1 * N_TILEB;
        uint32_t sbh = stg + 2 * N_TILEB;
        uint32_t sbl = stg + 3 * N_TILEB;

        #pragma unroll
        for (int kk = 0; kk < 2; kk++) {
            uint32_t ah[4][4], al[4][4], bh[4][2], bl[4][2];
            #pragma unroll
            for (int mt = 0; mt < 4; mt++) {
                uint32_t ra = (wm + mt * 16 + a_row) * STRB + kk * 32 + a_col;
                ldm_x4(ah[mt], sah + ra);
                ldm_x4(al[mt], sal + ra);
            }
            #pragma unroll
            for (int nt = 0; nt < 4; nt++) {
                uint32_t rb = (wn + nt * 8 + b_row) * STRB + kk * 32 + b_col;
                ldm_x2(bh[nt], sbh + rb);
                ldm_x2(bl[nt], sbl + rb);
            }
            #pragma unroll
            for (int mt = 0; mt < 4; mt++)
                #pragma unroll
                for (int nt = 0; nt < 4; nt++) {
                    mma_bf16(acc[mt][nt], ah[mt], bh[nt]);
                    mma_bf16(acc[mt][nt], ah[mt], bl[nt]);
                    mma_bf16(acc[mt][nt], al[mt], bh[nt]);
                }
        }
        __syncthreads();
    }

    int qm = lane >> 2, qn = 2 * (lane & 3);
    #pragma unroll
    for (int mt = 0; mt < 4; mt++) {
        #pragma unroll
        for (int nt = 0; nt < 4; nt++) {
            int m0 = bm + wm + mt * 16 + qm;
            int n0 = bn + wn + nt * 8 + qn;
            float b0 = bias[n0], b1 = bias[n0 + 1];
            #pragma unroll
            for (int half = 0; half < 2; half++) {
                int m = m0 + half * 8;
                if (m < M) {
                    float v0 = acc[mt][nt][half * 2 + 0] + b0;
                    float v1 = acc[mt][nt][half * 2 + 1] + b1;
                    if (EPI == 1) { v0 = gelu_f(v0); v1 = gelu_f(v1); }
                    *(float2*)(C + (size_t)m * N + n0) = make_float2(v0, v1);
                }
            }
        }
    }
}

// ================= wide GEMM: CTA tile 128x256, for N % 256 == 0 ============
// 256 threads, 8 warps of 32x128 (nt processed in groups of 4). Halves A reads.
#define W_ATILE (128 * STRB)            // 10240
#define W_BTILE (256 * STRB)            // 20480
#define W_OFF_AH 0
#define W_OFF_AL W_ATILE
#define W_OFF_BH (2 * W_ATILE)
#define W_OFF_BL (2 * W_ATILE + W_BTILE)
#define W_STAGEB (2 * W_ATILE + 2 * W_BTILE)   // 61440
#define W_GEMM_SMEM (2 * W_STAGEB)             // 122880

template<int EPI>
__global__ __launch_bounds__(256, 1) void gemm_wide(
        const __nv_bfloat16* __restrict__ Ah, const __nv_bfloat16* __restrict__ Al,
        const __nv_bfloat16* __restrict__ Bh, const __nv_bfloat16* __restrict__ Bl,
        const float* __restrict__ bias, float* __restrict__ C, int M, int N, int K) {
    extern __shared__ char smem[];
    uint32_t sb = smem_to_u32(smem);
    int tid = threadIdx.x, wid = tid >> 5, lane = tid & 31;
    int bm = blockIdx.y * 128, bn = blockIdx.x * 256;
    int wm = (wid & 3) * 32, wn = (wid >> 2) * 128;

    float acc[2][16][4];
    #pragma unroll
    for (int i = 0; i < 2; i++)
        #pragma unroll
        for (int j = 0; j < 16; j++)
            #pragma unroll
            for (int k = 0; k < 4; k++) acc[i][j][k] = 0.f;

    int row_ld = tid >> 2;          // 0..63
    int seg    = tid & 3;
    int nch = K >> 5;

    auto load_chunk = [&](int c, int s) {
        int k0 = c << 5;
        uint32_t base = sb + s * W_STAGEB;
        // A: rows row_ld, row_ld+64 (hi + lo)
        #pragma unroll
        for (int it = 0; it < 2; it++) {
            int row = row_ld + it * 64;
            uint32_t doff = row * STRB + seg * 16;
            int gm = bm + row;
            int sz = (gm < M) ? 16 : 0;
            int gmc = (gm < M) ? gm : (M - 1);
            const char* pa = (const char*)(Ah + (size_t)gmc * K + k0) + seg * 16;
            const char* pl = (const char*)(Al + (size_t)gmc * K + k0) + seg * 16;
            cp_async16z(base + W_OFF_AH + doff, pa, sz);
            cp_async16z(base + W_OFF_AL + doff, pl, sz);
        }
        // B: 256 rows (hi + lo)
        #pragma unroll
        for (int it = 0; it < 4; it++) {
            int row = row_ld + it * 64;
            uint32_t doff = row * STRB + seg * 16;
            int gn = bn + row;
            const char* pb = (const char*)(Bh + (size_t)gn * K + k0) + seg * 16;
            const char* pc = (const char*)(Bl + (size_t)gn * K + k0) + seg * 16;
            cp_async16(base + W_OFF_BH + doff, pb);
            cp_async16(base + W_OFF_BL + doff, pc);
        }
    };

    load_chunk(0, 0);
    asm volatile("cp.async.commit_group;");

    int a_row = lane & 15;
    int a_col = (lane >> 4) * 16;
    int b_row = lane & 7;
    int b_col = ((lane >> 3) & 1) * 16;

    for (int c = 0; c < nch; c++) {
        if (c + 1 < nch) {
            load_chunk(c + 1, (c + 1) & 1);
            asm volatile("cp.async.commit_group;");
            asm volatile("cp.async.wait_group 1;");
        } else {
            asm volatile("cp.async.wait_group 0;");
        }
        __syncthreads();

        uint32_t stg = sb + (c & 1) * W_STAGEB;
        uint32_t sah = stg + W_OFF_AH;
        uint32_t sal = stg + W_OFF_AL;
        uint32_t sbh = stg + W_OFF_BH;
        uint32_t sbl = stg + W_OFF_BL;

        #pragma unroll
        for (int kk = 0; kk < 2; kk++) {
            uint32_t ah[2][4], al[2][4];
            #pragma unroll
            for (int mt = 0; mt < 2; mt++) {
                uint32_t ra = (wm + mt * 16 + a_row) * STRB + kk * 32 + a_col;
                ldm_x4(ah[mt], sah + ra);
                ldm_x4(al[mt], sal + ra);
            }
            #pragma unroll
            for (int g = 0; g < 4; g++) {
                uint32_t bh[4][2], bl[4][2];
                #pragma unroll
                for (int nt = 0; nt < 4; nt++) {
                    uint32_t rb = (wn + g * 32 + nt * 8 + b_row) * STRB + kk * 32 + b_col;
                    ldm_x2(bh[nt], sbh + rb);
                    ldm_x2(bl[nt], sbl + rb);
                }
                #pragma unroll
                for (int mt = 0; mt < 2; mt++)
                    #pragma unroll
                    for (int nt = 0; nt < 4; nt++) {
                        mma_bf16(acc[mt][g * 4 + nt], ah[mt], bh[nt]);
                        mma_bf16(acc[mt][g * 4 + nt], ah[mt], bl[nt]);
                        mma_bf16(acc[mt][g * 4 + nt], al[mt], bh[nt]);
                    }
            }
        }
        __syncthreads();
    }

    int qm = lane >> 2, qn = 2 * (lane & 3);
    #pragma unroll
    for (int mt = 0; mt < 2; mt++) {
        #pragma unroll
        for (int nt = 0; nt < 16; nt++) {
            int m0 = bm + wm + mt * 16 + qm;
            int n0 = bn + wn + nt * 8 + qn;
            float b0 = bias[n0], b1 = bias[n0 + 1];
            #pragma unroll
            for (int half = 0; half < 2; half++) {
                int m = m0 + half * 8;
                if (m < M) {
                    float v0 = acc[mt][nt][half * 2 + 0] + b0;
                    float v1 = acc[mt][nt][half * 2 + 1] + b1;
                    if (EPI == 1) { v0 = gelu_f(v0); v1 = gelu_f(v1); }
                    *(float2*)(C + (size_t)m * N + n0) = make_float2(v0, v1);
                }
            }
        }
    }
}

// ---------------- attention: one block (128 thr) per destination node -------
__global__ void attn_kernel(const int* __restrict__ src, const float* __restrict__ e) {
    __shared__ float qs[DIMC];
    __shared__ float wm[4][4], wd[4][4];
    __shared__ float fm[4], fd[4];

    int node = blockIdx.x;
    int tid = threadIdx.x;
    int warp = tid >> 5, lane = tid & 31;
    int rs  = g_offsets[node];
    int deg = g_offsets[node + 1] - rs;

    if (deg == 0) {
        g_agg[(size_t)node * DIMC + tid]       = 0.f;
        g_agg[(size_t)node * DIMC + 128 + tid] = 0.f;
        return;
    }

    qs[tid]       = g_q[(size_t)node * DIMC + tid];
    qs[tid + 128] = g_q[(size_t)node * DIMC + 128 + tid];
    __syncthreads();

    float m[4] = {-1e30f, -1e30f, -1e30f, -1e30f};
    float den[4] = {0.f, 0.f, 0.f, 0.f};
    for (int j = warp; j < deg; j += 4) {
        int eid = g_perm[rs + j];
        int s = src[eid];
        const float* kp = g_kv + (size_t)s * (2 * DIMC);
        const float* ep = e + (size_t)eid * DIMC;
        float sh[4];
        #pragma unroll
        for (int h = 0; h < 4; h++) {
            int c = h * 64 + lane * 2;
            float2 kf = *(const float2*)(kp + c);
            float2 ef = *(const float2*)(ep + c);
            float2 qf = *(const float2*)(qs + c);
            sh[h] = (kf.x + ef.x) * qf.x + (kf.y + ef.y) * qf.y;
        }
        #pragma unroll
        for (int h = 0; h < 4; h++) {
            float v = sh[h];
            #pragma unroll
            for (int o = 16; o > 0; o >>= 1) v += __shfl_xor_sync(0xffffffff, v, o);
            sh[h] = v * 0.125f;
        }
        if (lane == 0) {
            *(float4*)(g_sim + (size_t)(rs + j) * 4) = make_float4(sh[0], sh[1], sh[2], sh[3]);
        }
        #pragma unroll
        for (int h = 0; h < 4; h++) {
            float mn = fmaxf(m[h], sh[h]);
            den[h] = den[h] * __expf(m[h] - mn) + __expf(sh[h] - mn);
            m[h] = mn;
        }
    }
    if (lane == 0) {
        #pragma unroll
        for (int h = 0; h < 4; h++) { wm[warp][h] = m[h]; wd[warp][h] = den[h]; }
    }
    __syncthreads();
    if (tid < 4) {
        int h = tid;
        float M_ = -1e30f;
        #pragma unroll
        for (int w = 0; w < 4; w++) M_ = fmaxf(M_, wm[w][h]);
        float D = 0.f;
        #pragma unroll
        for (int w = 0; w < 4; w++) D += wd[w][h] * __expf(wm[w][h] - M_);
        fm[h] = M_;
        fd[h] = D;
    }
    __syncthreads();

    int c0 = tid, c1 = tid + 128;
    int h0 = c0 >> 6, h1 = c1 >> 6;
    float rm0 = fm[h0], rm1 = fm[h1];
    float rd0 = 1.0f / fd[h0], rd1 = 1.0f / fd[h1];
    float acc0 = 0.f, acc1 = 0.f;
    for (int j = 0; j < deg; j++) {
        int eid = g_perm[rs + j];
        int s = src[eid];
        float p0 = __expf(g_sim[(size_t)(rs + j) * 4 + h0] - rm0) * rd0;
        float p1 = __expf(g_sim[(size_t)(rs + j) * 4 + h1] - rm1) * rd1;
        const float* vp = g_kv + (size_t)s * (2 * DIMC) + DIMC;
        const float* ep = e + (size_t)eid * DIMC;
        acc0 += p0 * (vp[c0] + ep[c0]);
        acc1 += p1 * (vp[c1] + ep[c1]);
    }
    g_agg[(size_t)node * DIMC + c0] = acc0;
    g_agg[(size_t)node * DIMC + c1] = acc1;
}

// ---------------- host orchestration ----------------
static inline dim3 grid_narrow(int M, int N) { return dim3(N / 128, (M + 127) / 128); }
static inline dim3 grid_wide(int M, int N)   { return dim3(N / 256, (M + 127) / 128); }

extern "C" void kernel_launch(void* const* d_in, const int* in_sizes, int n_in,
                              void* d_out, int out_size) {
    const float* x         = (const float*)d_in[0];
    const float* edge_attr = (const float*)d_in[1];
    const int*   edge_idx  = (const int*)  d_in[2];
    const float* ln1_g     = (const float*)d_in[3];
    const float* ln1_b     = (const float*)d_in[4];
    const float* Wq        = (const float*)d_in[5];
    const float* bq        = (const float*)d_in[6];
    const float* Wkv       = (const float*)d_in[7];
    const float* bkv       = (const float*)d_in[8];
    const float* We        = (const float*)d_in[9];
    const float* be        = (const float*)d_in[10];
    const float* Wo        = (const float*)d_in[11];
    const float* bo        = (const float*)d_in[12];
    const float* gate_attn = (const float*)d_in[13];
    const float* ln2_g     = (const float*)d_in[14];
    const float* ln2_b     = (const float*)d_in[15];
    const float* Wff1      = (const float*)d_in[16];
    const float* bff1      = (const float*)d_in[17];
    const float* Wff2      = (const float*)d_in[18];
    const float* bff2      = (const float*)d_in[19];
    const float* gate_ff   = (const float*)d_in[20];
    const float* Wproj     = (const float*)d_in[21];
    const float* bproj     = (const float*)d_in[22];

    const int* src_arr = edge_idx;
    const int* dst_arr = edge_idx + EDGES;

    cudaFuncSetAttribute(gemm_mma<0>,  cudaFuncAttributeMaxDynamicSharedMemorySize, N_GEMM_SMEM);
    cudaFuncSetAttribute(gemm_wide<0>, cudaFuncAttributeMaxDynamicSharedMemorySize, W_GEMM_SMEM);
    cudaFuncSetAttribute(gemm_wide<1>, cudaFuncAttributeMaxDynamicSharedMemorySize, W_GEMM_SMEM);

    float *p_xbuf, *p_xn, *p_q, *p_kv, *p_e, *p_agg, *p_y, *p_ff;
    __nv_bfloat16 *p_ah, *p_al, *p_eah, *p_eal, *p_wh, *p_wl;
    cudaGetSymbolAddress((void**)&p_xbuf, g_xbuf);
    cudaGetSymbolAddress((void**)&p_xn,   g_xn);
    cudaGetSymbolAddress((void**)&p_q,    g_q);
    cudaGetSymbolAddress((void**)&p_kv,   g_kv);
    cudaGetSymbolAddress((void**)&p_e,    g_e);
    cudaGetSymbolAddress((void**)&p_agg,  g_agg);
    cudaGetSymbolAddress((void**)&p_y,    g_y);
    cudaGetSymbolAddress((void**)&p_ff,   g_ff);
    cudaGetSymbolAddress((void**)&p_ah,   g_act_h);
    cudaGetSymbolAddress((void**)&p_al,   g_act_l);
    cudaGetSymbolAddress((void**)&p_eah,  g_ea_h);
    cudaGetSymbolAddress((void**)&p_eal,  g_ea_l);
    cudaGetSymbolAddress((void**)&p_wh,   g_wh);
    cudaGetSymbolAddress((void**)&p_wl,   g_wl);

    dim3 tb(32, 8);
    int n4_ea = EDGES * EDIM / 4;

    // ---- front-load the edge pipeline (also puts heavy kernels at ncu -s 5) ----
    copy_kernel<<<(NODES * DIMC + 255) / 256, 256>>>(x, p_xbuf, NODES * DIMC);                      // 1
    split_kernel<<<(n4_ea + 255) / 256, 256>>>(edge_attr, p_eah, p_eal, n4_ea);                     // 2
    tsplit_kernel<<<dim3(INNER/32, EDIM/32), tb>>>(We,                       p_wh + WOFF_E,          p_wl + WOFF_E,          EDIM, INNER);   // 3
    tsplit_kernel<<<dim3(INNER/32, EDIM/32), tb>>>(We + (size_t)EDIM*INNER,  p_wh + WLAYER + WOFF_E, p_wl + WLAYER + WOFF_E, EDIM, INNER);   // 4
    // both layers' e (independent of x) — heavy launches 5 & 6
    gemm_wide<0><<<grid_wide(EDGES, INNER), 256, W_GEMM_SMEM>>>(
        p_eah, p_eal, p_wh + WOFF_E, p_wl + WOFF_E, be, p_e, EDGES, INNER, EDIM);                   // 5
    gemm_wide<0><<<grid_wide(EDGES, INNER), 256, W_GEMM_SMEM>>>(
        p_eah, p_eal, p_wh + WLAYER + WOFF_E, p_wl + WLAYER + WOFF_E, be + INNER,
        p_e + (size_t)EDGES * DIMC, EDGES, INNER, EDIM);                                            // 6

    // CSR of incoming edges
    zero_counts_kernel<<<(NODES + 255) / 256, 256>>>();
    count_kernel<<<(EDGES + 255) / 256, 256>>>(dst_arr);
    scan_kernel<<<1, 1024>>>();
    cursor_init_kernel<<<(NODES + 255) / 256, 256>>>();
    scatter_kernel<<<(EDGES + 255) / 256, 256>>>(dst_arr);

    // remaining weight transposes
    for (int d = 0; d < DEPTH; d++) {
        size_t wb = (size_t)d * WLAYER;
        tsplit_kernel<<<dim3(INNER/32,  DIMC/32),  tb>>>(Wq   + (size_t)d*DIMC*INNER,   p_wh + wb + WOFF_Q,  p_wl + wb + WOFF_Q,  DIMC,  INNER);
        tsplit_kernel<<<dim3(2*INNER/32,DIMC/32),  tb>>>(Wkv  + (size_t)d*DIMC*2*INNER, p_wh + wb + WOFF_KV, p_wl + wb + WOFF_KV, DIMC,  2*INNER);
        tsplit_kernel<<<dim3(DIMC/32,   INNER/32), tb>>>(Wo   + (size_t)d*INNER*DIMC,   p_wh + wb + WOFF_O,  p_wl + wb + WOFF_O,  INNER, DIMC);
        tsplit_kernel<<<dim3(FFDIM/32,  DIMC/32),  tb>>>(Wff1 + (size_t)d*DIMC*FFDIM,   p_wh + wb + WOFF_F1, p_wl + wb + WOFF_F1, DIMC,  FFDIM);
        tsplit_kernel<<<dim3(DIMC/32,   FFDIM/32), tb>>>(Wff2 + (size_t)d*FFDIM*DIMC,   p_wh + wb + WOFF_F2, p_wl + wb + WOFF_F2, FFDIM, DIMC);
    }
    tsplit_kernel<<<dim3(OUTC/32, DIMC/32), tb>>>(Wproj, p_wh + WOFF_P, p_wl + WOFF_P, DIMC, OUTC);

    int warps_rows_blocks = (NODES + 7) / 8;
    int n4_xn = NODES * DIMC / 4;
    int n4_ff = NODES * FFDIM / 4;

    for (int d = 0; d < DEPTH; d++) {
        size_t wb = (size_t)d * WLAYER;
        // pre-norm + split
        ln_kernel<<<warps_rows_blocks, 256>>>(p_xbuf, ln1_g + d * DIMC, ln1_b + d * DIMC, p_xn);
        split_kernel<<<(n4_xn + 255) / 256, 256>>>(p_xn, p_ah, p_al, n4_xn);
        // projections
        gemm_wide<0><<<grid_wide(NODES, INNER), 256, W_GEMM_SMEM>>>(
            p_ah, p_al, p_wh + wb + WOFF_Q, p_wl + wb + WOFF_Q, bq + d * INNER, p_q, NODES, INNER, DIMC);
        gemm_wide<0><<<grid_wide(NODES, 2 * INNER), 256, W_GEMM_SMEM>>>(
            p_ah, p_al, p_wh + wb + WOFF_KV, p_wl + wb + WOFF_KV, bkv + d * 2 * INNER, p_kv, NODES, 2 * INNER, DIMC);
        // sparse attention (e for this layer precomputed)
        attn_kernel<<<NODES, 128>>>(src_arr, p_e + (size_t)d * EDGES * DIMC);
        // output projection + gated residual
        split_kernel<<<(n4_xn + 255) / 256, 256>>>(p_agg, p_ah, p_al, n4_xn);
        gemm_mma<0><<<grid_narrow(NODES, DIMC), 256, N_GEMM_SMEM>>>(
            p_ah, p_al, p_wh + wb + WOFF_O, p_wl + wb + WOFF_O, bo + d * DIMC, p_y, NODES, DIMC, INNER);
        gated_residual_kernel<<<warps_rows_blocks, 256>>>(p_y, p_xbuf, gate_attn + (size_t)d * 3 * DIMC);
        // feedforward
        ln_kernel<<<warps_rows_blocks, 256>>>(p_xbuf, ln2_g + d * DIMC, ln2_b + d * DIMC, p_xn);
        split_kernel<<<(n4_xn + 255) / 256, 256>>>(p_xn, p_ah, p_al, n4_xn);
        gemm_wide<1><<<grid_wide(NODES, FFDIM), 256, W_GEMM_SMEM>>>(
            p_ah, p_al, p_wh + wb + WOFF_F1, p_wl + wb + WOFF_F1, bff1 + d * FFDIM, p_ff, NODES, FFDIM, DIMC);
        split_kernel<<<(n4_ff + 255) / 256, 256>>>(p_ff, p_ah, p_al, n4_ff);
        gemm_wide<0><<<grid_wide(NODES, DIMC), 256, W_GEMM_SMEM>>>(
            p_ah, p_al, p_wh + wb + WOFF_F2, p_wl + wb + WOFF_F2, bff2 + d * DIMC, p_y, NODES, DIMC, FFDIM);
        gated_residual_kernel<<<warps_rows_blocks, 256>>>(p_y, p_xbuf, gate_ff + (size_t)d * 3 * DIMC);
    }

    // final projection
    split_kernel<<<(n4_xn + 255) / 256, 256>>>(p_xbuf, p_ah, p_al, n4_xn);
    gemm_mma<0><<<grid_narrow(NODES, OUTC), 256, N_GEMM_SMEM>>>(
        p_ah, p_al, p_wh + WOFF_P, p_wl + WOFF_P, bproj, (float*)d_out, NODES, OUTC, DIMC);
}

// round 14
// speedup vs baseline: 1.4174x; 1.0377x over previous
#include <cuda_runtime.h>
#include <cuda_bf16.h>
#include <math.h>
#include <stdint.h>

// ---------------- problem constants ----------------
#define NODES   20000
#define EDGES   200000
#define DIMC    256
#define HEADS   4
#define DH      64
#define INNER   256
#define EDIM    512
#define FFDIM   1024
#define OUTC    128
#define DEPTH   2

// ---------------- scratch (device globals; no allocation allowed) ----------
__device__ float g_xbuf[NODES * DIMC];
__device__ float g_xn  [NODES * DIMC];
__device__ float g_q   [NODES * DIMC];
__device__ float g_kv  [NODES * 2 * DIMC];
__device__ __nv_bfloat16 g_e[(size_t)EDGES * 512];   // both layers, bf16, [E,512]
__device__ float g_sim [(size_t)EDGES * HEADS];
__device__ float g_agg [NODES * DIMC];
__device__ float g_y   [NODES * DIMC];
__device__ float g_ff  [NODES * FFDIM];
__device__ int   g_counts [NODES];
__device__ int   g_offsets[NODES + 1];
__device__ int   g_cursor [NODES];
__device__ int   g_perm   [EDGES];

// bf16 split buffers (hi/lo)
__device__ __nv_bfloat16 g_act_h[(size_t)NODES * FFDIM];
__device__ __nv_bfloat16 g_act_l[(size_t)NODES * FFDIM];
__device__ __nv_bfloat16 g_ea_h [(size_t)EDGES * EDIM];
__device__ __nv_bfloat16 g_ea_l [(size_t)EDGES * EDIM];

// stacked We^T (both layers): [512 rows, 512 cols] bf16 hi/lo
__device__ __nv_bfloat16 g_weh[512 * 512];
__device__ __nv_bfloat16 g_wel[512 * 512];

// transposed split weights, [N,K] bf16, per-layer packed (non-edge)
// sizes: Q 65536, KV 131072, O 65536, F1 262144, F2 262144  -> 786432/layer
#define WOFF_Q   0
#define WOFF_KV  65536
#define WOFF_O   196608
#define WOFF_F1  262144
#define WOFF_F2  524288
#define WLAYER   786432
#define WOFF_P   (2 * WLAYER)
#define WTOT     (WOFF_P + 32768)
__device__ __nv_bfloat16 g_wh[WTOT];
__device__ __nv_bfloat16 g_wl[WTOT];

__device__ __forceinline__ uint32_t smem_to_u32(const void* p) {
    uint32_t a;
    asm("{ .reg .u64 t; cvta.to.shared.u64 t, %1; cvt.u32.u64 %0, t; }" : "=r"(a) : "l"(p));
    return a;
}

// ---------------- small utility kernels ----------------
__global__ void copy_kernel(const float* __restrict__ src, float* __restrict__ dst, int n) {
    int i = blockIdx.x * blockDim.x + threadIdx.x;
    if (i < n) dst[i] = src[i];
}

__global__ void zero_counts_kernel() {
    int i = blockIdx.x * blockDim.x + threadIdx.x;
    if (i < NODES) g_counts[i] = 0;
}

__global__ void count_kernel(const int* __restrict__ dst) {
    int e = blockIdx.x * blockDim.x + threadIdx.x;
    if (e < EDGES) atomicAdd(&g_counts[dst[e]], 1);
}

// single-block exclusive scan, warp-scan based (1024 threads)
__global__ void scan_kernel() {
    __shared__ int wsum[32];
    const int CHUNK = 20;
    int tid = threadIdx.x, lane = tid & 31, wid = tid >> 5;
    int base = tid * CHUNK;
    int s = 0;
    #pragma unroll
    for (int i = 0; i < CHUNK; i++) {
        int idx = base + i;
        s += (idx < NODES) ? g_counts[idx] : 0;
    }
    int inc = s;
    #pragma unroll
    for (int o = 1; o < 32; o <<= 1) {
        int t = __shfl_up_sync(0xffffffff, inc, o);
        if (lane >= o) inc += t;
    }
    if (lane == 31) wsum[wid] = inc;
    __syncthreads();
    if (wid == 0) {
        int v = wsum[lane];
        int inc2 = v;
        #pragma unroll
        for (int o = 1; o < 32; o <<= 1) {
            int t = __shfl_up_sync(0xffffffff, inc2, o);
            if (lane >= o) inc2 += t;
        }
        wsum[lane] = inc2 - v;
    }
    __syncthreads();
    int run = wsum[wid] + (inc - s);
    #pragma unroll
    for (int i = 0; i < CHUNK; i++) {
        int idx = base + i;
        if (idx <= NODES) g_offsets[idx] = run;
        run += (idx < NODES) ? g_counts[idx] : 0;
    }
}

__global__ void cursor_init_kernel() {
    int i = blockIdx.x * blockDim.x + threadIdx.x;
    if (i < NODES) g_cursor[i] = g_offsets[i];
}

__global__ void scatter_kernel(const int* __restrict__ dst) {
    int e = blockIdx.x * blockDim.x + threadIdx.x;
    if (e < EDGES) {
        int pos = atomicAdd(&g_cursor[dst[e]], 1);
        g_perm[pos] = e;
    }
}

// ---------------- bf16 split (hi + lo) elementwise ----------
__global__ void split_kernel(const float* __restrict__ x, __nv_bfloat16* __restrict__ h,
                             __nv_bfloat16* __restrict__ l, int n4) {
    int i = blockIdx.x * blockDim.x + threadIdx.x;
    if (i >= n4) return;
    float4 v = ((const float4*)x)[i];
    float vv[4] = {v.x, v.y, v.z, v.w};
    uint16_t hs[4], ls[4];
    #pragma unroll
    for (int j = 0; j < 4; j++) {
        __nv_bfloat16 hb = __float2bfloat16(vv[j]);
        __nv_bfloat16 lb = __float2bfloat16(vv[j] - __bfloat162float(hb));
        hs[j] = __bfloat16_as_ushort(hb);
        ls[j] = __bfloat16_as_ushort(lb);
    }
    ((uint2*)h)[i] = make_uint2((uint32_t)hs[0] | ((uint32_t)hs[1] << 16),
                                (uint32_t)hs[2] | ((uint32_t)hs[3] << 16));
    ((uint2*)l)[i] = make_uint2((uint32_t)ls[0] | ((uint32_t)ls[1] << 16),
                                (uint32_t)ls[2] | ((uint32_t)ls[3] << 16));
}

// ---------------- weight transpose + split: [K,N] fp32 -> [N,K] bf16 hi/lo --
__global__ void tsplit_kernel(const float* __restrict__ W, __nv_bfloat16* __restrict__ Th,
                              __nv_bfloat16* __restrict__ Tl, int K, int N) {
    __shared__ float t[32][33];
    int kb = blockIdx.y << 5, nb = blockIdx.x << 5;
    int tx = threadIdx.x, ty = threadIdx.y;  // 32 x 8
    #pragma unroll
    for (int i = 0; i < 32; i += 8)
        t[ty + i][tx] = W[(size_t)(kb + ty + i) * N + nb + tx];
    __syncthreads();
    #pragma unroll
    for (int i = 0; i < 32; i += 8) {
        int n = nb + ty + i, k = kb + tx;
        float v = t[tx][ty + i];
        __nv_bfloat16 hb = __float2bfloat16(v);
        Th[(size_t)n * K + k] = hb;
        Tl[(size_t)n * K + k] = __float2bfloat16(v - __bfloat162float(hb));
    }
}

// ---------------- LayerNorm: warp per row ----------------
__global__ void ln_kernel(const float* __restrict__ x, const float* __restrict__ g,
                          const float* __restrict__ b, float* __restrict__ out) {
    int row = blockIdx.x * (blockDim.x >> 5) + (threadIdx.x >> 5);
    if (row >= NODES) return;
    int lane = threadIdx.x & 31;
    const float* xr = x + (size_t)row * DIMC;
    float vals[8];
    float4 v0 = *(const float4*)(xr + lane * 8);
    float4 v1 = *(const float4*)(xr + lane * 8 + 4);
    vals[0]=v0.x; vals[1]=v0.y; vals[2]=v0.z; vals[3]=v0.w;
    vals[4]=v1.x; vals[5]=v1.y; vals[6]=v1.z; vals[7]=v1.w;
    float s = 0.f, ss = 0.f;
    #pragma unroll
    for (int i = 0; i < 8; i++) { s += vals[i]; ss += vals[i] * vals[i]; }
    #pragma unroll
    for (int o = 16; o > 0; o >>= 1) {
        s  += __shfl_xor_sync(0xffffffff, s,  o);
        ss += __shfl_xor_sync(0xffffffff, ss, o);
    }
    float mean = s * (1.0f / DIMC);
    float var  = ss * (1.0f / DIMC) - mean * mean;
    float rstd = rsqrtf(var + 1e-5f);
    float* orow = out + (size_t)row * DIMC;
    #pragma unroll
    for (int i = 0; i < 8; i++) {
        int c = lane * 8 + i;
        orow[c] = (vals[i] - mean) * rstd * g[c] + b[c];
    }
}

// ---------------- gated residual: warp per row ----------------
__global__ void gated_residual_kernel(const float* __restrict__ y, float* __restrict__ res,
                                      const float* __restrict__ gw) {
    int row = blockIdx.x * (blockDim.x >> 5) + (threadIdx.x >> 5);
    if (row >= NODES) return;
    int lane = threadIdx.x & 31;
    const float* yr = y   + (size_t)row * DIMC;
    float*       rr = res + (size_t)row * DIMC;
    float yv[8], rv[8];
    float z = 0.f;
    #pragma unroll
    for (int i = 0; i < 8; i++) {
        int c = lane * 8 + i;
        yv[i] = yr[c];
        rv[i] = rr[c];
        float w1 = gw[c], w2 = gw[DIMC + c], w3 = gw[2 * DIMC + c];
        z += yv[i] * (w1 + w3) + rv[i] * (w2 - w3);
    }
    #pragma unroll
    for (int o = 16; o > 0; o >>= 1) z += __shfl_xor_sync(0xffffffff, z, o);
    float gate = 1.0f / (1.0f + __expf(-z));
    #pragma unroll
    for (int i = 0; i < 8; i++) {
        int c = lane * 8 + i;
        rr[c] = yv[i] * gate + rv[i] * (1.0f - gate);
    }
}

// ---------------- common MMA helpers ----------------
__device__ __forceinline__ float gelu_f(float v) {
    float c = 0.7978845608028654f * (v + 0.044715f * v * v * v);
    return 0.5f * v * (1.0f + tanhf(c));
}
__device__ __forceinline__ void cp_async16z(uint32_t dst, const void* src, int sz) {
    asm volatile("cp.async.cg.shared.global [%0], [%1], 16, %2;"
                 :: "r"(dst), "l"(src), "r"(sz));
}
__device__ __forceinline__ void cp_async16(uint32_t dst, const void* src) {
    asm volatile("cp.async.cg.shared.global [%0], [%1], 16;" :: "r"(dst), "l"(src));
}
__device__ __forceinline__ void ldm_x4(uint32_t* r, uint32_t addr) {
    asm volatile("ldmatrix.sync.aligned.m8n8.x4.shared.b16 {%0,%1,%2,%3}, [%4];"
                 : "=r"(r[0]), "=r"(r[1]), "=r"(r[2]), "=r"(r[3]) : "r"(addr));
}
__device__ __forceinline__ void ldm_x2(uint32_t* r, uint32_t addr) {
    asm volatile("ldmatrix.sync.aligned.m8n8.x2.shared.b16 {%0,%1}, [%2];"
                 : "=r"(r[0]), "=r"(r[1]) : "r"(addr));
}
__device__ __forceinline__ void mma_bf16(float* d, const uint32_t* a, const uint32_t* b) {
    asm volatile("mma.sync.aligned.m16n8k16.row.col.f32.bf16.bf16.f32 "
                 "{%0,%1,%2,%3}, {%4,%5,%6,%7}, {%8,%9}, {%0,%1,%2,%3};"
                 : "+f"(d[0]), "+f"(d[1]), "+f"(d[2]), "+f"(d[3])
                 : "r"(a[0]), "r"(a[1]), "r"(a[2]), "r"(a[3]), "r"(b[0]), "r"(b[1]));
}

#define STRB 80                       // smem bytes per 32-col bf16 row (64B + 16 pad)

// ================= narrow GEMM: CTA tile 128x128, for N=128 outputs =========
#define N_TILEB (128 * STRB)
#define N_STAGEB (4 * N_TILEB)
#define N_GEMM_SMEM (2 * N_STAGEB)      // 81920 B

template<int EPI>
__global__ __launch_bounds__(256, 1) void gemm_mma(
        const __nv_bfloat16* __restrict__ Ah, const __nv_bfloat16* __restrict__ Al,
        const __nv_bfloat16* __restrict__ Bh, const __nv_bfloat16* __restrict__ Bl,
        const float* __restrict__ bias, float* __restrict__ C, int M, int N, int K) {
    extern __shared__ char smem[];
    uint32_t sb = smem_to_u32(smem);
    int tid = threadIdx.x, wid = tid >> 5, lane = tid & 31;
    int bm = blockIdx.y * 128, bn = blockIdx.x * 128;
    int wm = (wid & 1) * 64, wn = (wid >> 1) * 32;

    float acc[4][4][4];
    #pragma unroll
    for (int i = 0; i < 4; i++)
        #pragma unroll
        for (int j = 0; j < 4; j++)
            #pragma unroll
            for (int k = 0; k < 4; k++) acc[i][j][k] = 0.f;

    int row_ld = tid >> 2;
    int seg    = tid & 3;
    int nch = K >> 5;

    auto load_chunk = [&](int c, int s) {
        int k0 = c << 5;
        uint32_t base = sb + s * N_STAGEB;
        #pragma unroll
        for (int it = 0; it < 2; it++) {
            int row = row_ld + it * 64;
            uint32_t doff = row * STRB + seg * 16;
            int gm = bm + row;
            int sz = (gm < M) ? 16 : 0;
            int gmc = (gm < M) ? gm : (M - 1);
            const char* pa = (const char*)(Ah + (size_t)gmc * K + k0) + seg * 16;
            const char* pl = (const char*)(Al + (size_t)gmc * K + k0) + seg * 16;
            cp_async16z(base + 0 * N_TILEB + doff, pa, sz);
            cp_async16z(base + 1 * N_TILEB + doff, pl, sz);
            int gn = bn + row;
            const char* pb = (const char*)(Bh + (size_t)gn * K + k0) + seg * 16;
            const char* pc = (const char*)(Bl + (size_t)gn * K + k0) + seg * 16;
            cp_async16(base + 2 * N_TILEB + doff, pb);
            cp_async16(base + 3 * N_TILEB + doff, pc);
        }
    };

    load_chunk(0, 0);
    asm volatile("cp.async.commit_group;");

    int a_row = lane & 15;
    int a_col = (lane >> 4) * 16;
    int b_row = lane & 7;
    int b_col = ((lane >> 3) & 1) * 16;

    for (int c = 0; c < nch; c++) {
        if (c + 1 < nch) {
            load_chunk(c + 1, (c + 1) & 1);
            asm volatile("cp.async.commit_group;");
            asm volatile("cp.async.wait_group 1;");
        } else {
            asm volatile("cp.async.wait_group 0;");
        }
        __syncthreads();

        uint32_t stg = sb + (c & 1) * N_STAGEB;
        uint32_t sah = stg + 0 * N_TILEB;
        uint32_t sal = stg + 1 * N_TILEB;
        uint32_t sbh = stg + 2 * N_TILEB;
        uint32_t sbl = stg + 3 * N_TILEB;

        #pragma unroll
        for (int kk = 0; kk < 2; kk++) {
            uint32_t ah[4][4], al[4][4], bh[4][2], bl[4][2];
            #pragma unroll
            for (int mt = 0; mt < 4; mt++) {
                uint32_t ra = (wm + mt * 16 + a_row) * STRB + kk * 32 + a_col;
                ldm_x4(ah[mt], sah + ra);
                ldm_x4(al[mt], sal + ra);
            }
            #pragma unroll
            for (int nt = 0; nt < 4; nt++) {
                uint32_t rb = (wn + nt * 8 + b_row) * STRB + kk * 32 + b_col;
                ldm_x2(bh[nt], sbh + rb);
                ldm_x2(bl[nt], sbl + rb);
            }
            #pragma unroll
            for (int mt = 0; mt < 4; mt++)
                #pragma unroll
                for (int nt = 0; nt < 4; nt++) {
                    mma_bf16(acc[mt][nt], ah[mt], bh[nt]);
                    mma_bf16(acc[mt][nt], ah[mt], bl[nt]);
                    mma_bf16(acc[mt][nt], al[mt], bh[nt]);
                }
        }
        __syncthreads();
    }

    int qm = lane >> 2, qn = 2 * (lane & 3);
    #pragma unroll
    for (int mt = 0; mt < 4; mt++) {
        #pragma unroll
        for (int nt = 0; nt < 4; nt++) {
            int m0 = bm + wm + mt * 16 + qm;
            int n0 = bn + wn + nt * 8 + qn;
            float b0 = bias[n0], b1 = bias[n0 + 1];
            #pragma unroll
            for (int half = 0; half < 2; half++) {
                int m = m0 + half * 8;
                if (m < M) {
                    float v0 = acc[mt][nt][half * 2 + 0] + b0;
                    float v1 = acc[mt][nt][half * 2 + 1] + b1;
                    if (EPI == 1) { v0 = gelu_f(v0); v1 = gelu_f(v1); }
                    *(float2*)(C + (size_t)m * N + n0) = make_float2(v0, v1);
                }
            }
        }
    }
}

// ================= wide GEMM: CTA tile 128x256 =============================
// EPI: 0 = fp32 out, 1 = gelu fp32 out, 2 = bf16 out (fused e-GEMM)
#define W_ATILE (128 * STRB)
#define W_BTILE (256 * STRB)
#define W_OFF_AH 0
#define W_OFF_AL W_ATILE
#define W_OFF_BH (2 * W_ATILE)
#define W_OFF_BL (2 * W_ATILE + W_BTILE)
#define W_STAGEB (2 * W_ATILE + 2 * W_BTILE)
#define W_GEMM_SMEM (2 * W_STAGEB)             // 122880

template<int EPI>
__global__ __launch_bounds__(256, 1) void gemm_wide(
        const __nv_bfloat16* __restrict__ Ah, const __nv_bfloat16* __restrict__ Al,
        const __nv_bfloat16* __restrict__ Bh, const __nv_bfloat16* __restrict__ Bl,
        const float* __restrict__ bias, void* __restrict__ Cv, int M, int N, int K) {
    extern __shared__ char smem[];
    uint32_t sb = smem_to_u32(smem);
    int tid = threadIdx.x, wid = tid >> 5, lane = tid & 31;
    int bm = blockIdx.y * 128, bn = blockIdx.x * 256;
    int wm = (wid & 3) * 32, wn = (wid >> 2) * 128;

    float acc[2][16][4];
    #pragma unroll
    for (int i = 0; i < 2; i++)
        #pragma unroll
        for (int j = 0; j < 16; j++)
            #pragma unroll
            for (int k = 0; k < 4; k++) acc[i][j][k] = 0.f;

    int row_ld = tid >> 2;
    int seg    = tid & 3;
    int nch = K >> 5;

    auto load_chunk = [&](int c, int s) {
        int k0 = c << 5;
        uint32_t base = sb + s * W_STAGEB;
        #pragma unroll
        for (int it = 0; it < 2; it++) {
            int row = row_ld + it * 64;
            uint32_t doff = row * STRB + seg * 16;
            int gm = bm + row;
            int sz = (gm < M) ? 16 : 0;
            int gmc = (gm < M) ? gm : (M - 1);
            const char* pa = (const char*)(Ah + (size_t)gmc * K + k0) + seg * 16;
            const char* pl = (const char*)(Al + (size_t)gmc * K + k0) + seg * 16;
            cp_async16z(base + W_OFF_AH + doff, pa, sz);
            cp_async16z(base + W_OFF_AL + doff, pl, sz);
        }
        #pragma unroll
        for (int it = 0; it < 4; it++) {
            int row = row_ld + it * 64;
            uint32_t doff = row * STRB + seg * 16;
            int gn = bn + row;
            const char* pb = (const char*)(Bh + (size_t)gn * K + k0) + seg * 16;
            const char* pc = (const char*)(Bl + (size_t)gn * K + k0) + seg * 16;
            cp_async16(base + W_OFF_BH + doff, pb);
            cp_async16(base + W_OFF_BL + doff, pc);
        }
    };

    load_chunk(0, 0);
    asm volatile("cp.async.commit_group;");

    int a_row = lane & 15;
    int a_col = (lane >> 4) * 16;
    int b_row = lane & 7;
    int b_col = ((lane >> 3) & 1) * 16;

    for (int c = 0; c < nch; c++) {
        if (c + 1 < nch) {
            load_chunk(c + 1, (c + 1) & 1);
            asm volatile("cp.async.commit_group;");
            asm volatile("cp.async.wait_group 1;");
        } else {
            asm volatile("cp.async.wait_group 0;");
        }
        __syncthreads();

        uint32_t stg = sb + (c & 1) * W_STAGEB;
        uint32_t sah = stg + W_OFF_AH;
        uint32_t sal = stg + W_OFF_AL;
        uint32_t sbh = stg + W_OFF_BH;
        uint32_t sbl = stg + W_OFF_BL;

        #pragma unroll
        for (int kk = 0; kk < 2; kk++) {
            uint32_t ah[2][4], al[2][4];
            #pragma unroll
            for (int mt = 0; mt < 2; mt++) {
                uint32_t ra = (wm + mt * 16 + a_row) * STRB + kk * 32 + a_col;
                ldm_x4(ah[mt], sah + ra);
                ldm_x4(al[mt], sal + ra);
            }
            #pragma unroll
            for (int g = 0; g < 4; g++) {
                uint32_t bh[4][2], bl[4][2];
                #pragma unroll
                for (int nt = 0; nt < 4; nt++) {
                    uint32_t rb = (wn + g * 32 + nt * 8 + b_row) * STRB + kk * 32 + b_col;
                    ldm_x2(bh[nt], sbh + rb);
                    ldm_x2(bl[nt], sbl + rb);
                }
                #pragma unroll
                for (int mt = 0; mt < 2; mt++)
                    #pragma unroll
                    for (int nt = 0; nt < 4; nt++) {
                        mma_bf16(acc[mt][g * 4 + nt], ah[mt], bh[nt]);
                        mma_bf16(acc[mt][g * 4 + nt], ah[mt], bl[nt]);
                        mma_bf16(acc[mt][g * 4 + nt], al[mt], bh[nt]);
                    }
            }
        }
        __syncthreads();
    }

    int qm = lane >> 2, qn = 2 * (lane & 3);
    float* C = (float*)Cv;
    __nv_bfloat16* Cb = (__nv_bfloat16*)Cv;
    #pragma unroll
    for (int mt = 0; mt < 2; mt++) {
        #pragma unroll
        for (int nt = 0; nt < 16; nt++) {
            int m0 = bm + wm + mt * 16 + qm;
            int n0 = bn + wn + nt * 8 + qn;
            float b0 = bias[n0], b1 = bias[n0 + 1];
            #pragma unroll
            for (int half = 0; half < 2; half++) {
                int m = m0 + half * 8;
                if (m < M) {
                    float v0 = acc[mt][nt][half * 2 + 0] + b0;
                    float v1 = acc[mt][nt][half * 2 + 1] + b1;
                    if (EPI == 1) { v0 = gelu_f(v0); v1 = gelu_f(v1); }
                    if (EPI == 2) {
                        uint32_t pk = (uint32_t)__bfloat16_as_ushort(__float2bfloat16(v0)) |
                                      ((uint32_t)__bfloat16_as_ushort(__float2bfloat16(v1)) << 16);
                        *(uint32_t*)(Cb + (size_t)m * N + n0) = pk;
                    } else {
                        *(float2*)(C + (size_t)m * N + n0) = make_float2(v0, v1);
                    }
                }
            }
        }
    }
}

// ---------------- attention: one block (128 thr) per destination node -------
// e: bf16, row stride 512 (layer column offset baked into pointer)
__global__ void attn_kernel(const int* __restrict__ src, const __nv_bfloat16* __restrict__ e) {
    __shared__ float qs[DIMC];
    __shared__ float wm[4][4], wd[4][4];
    __shared__ float fm[4], fd[4];

    int node = blockIdx.x;
    int tid = threadIdx.x;
    int warp = tid >> 5, lane = tid & 31;
    int rs  = g_offsets[node];
    int deg = g_offsets[node + 1] - rs;

    if (deg == 0) {
        g_agg[(size_t)node * DIMC + tid]       = 0.f;
        g_agg[(size_t)node * DIMC + 128 + tid] = 0.f;
        return;
    }

    qs[tid]       = g_q[(size_t)node * DIMC + tid];
    qs[tid + 128] = g_q[(size_t)node * DIMC + 128 + tid];
    __syncthreads();

    float m[4] = {-1e30f, -1e30f, -1e30f, -1e30f};
    float den[4] = {0.f, 0.f, 0.f, 0.f};
    for (int j = warp; j < deg; j += 4) {
        int eid = g_perm[rs + j];
        int s = src[eid];
        const float* kp = g_kv + (size_t)s * (2 * DIMC);
        const __nv_bfloat16* ep = e + (size_t)eid * 512;
        float sh[4];
        #pragma unroll
        for (int h = 0; h < 4; h++) {
            int c = h * 64 + lane * 2;
            float2 kf = *(const float2*)(kp + c);
            __nv_bfloat162 ef2 = *(const __nv_bfloat162*)(ep + c);
            float2 qf = *(const float2*)(qs + c);
            sh[h] = (kf.x + __bfloat162float(ef2.x)) * qf.x +
                    (kf.y + __bfloat162float(ef2.y)) * qf.y;
        }
        #pragma unroll
        for (int h = 0; h < 4; h++) {
            float v = sh[h];
            #pragma unroll
            for (int o = 16; o > 0; o >>= 1) v += __shfl_xor_sync(0xffffffff, v, o);
            sh[h] = v * 0.125f;
        }
        if (lane == 0) {
            *(float4*)(g_sim + (size_t)(rs + j) * 4) = make_float4(sh[0], sh[1], sh[2], sh[3]);
        }
        #pragma unroll
        for (int h = 0; h < 4; h++) {
            float mn = fmaxf(m[h], sh[h]);
            den[h] = den[h] * __expf(m[h] - mn) + __expf(sh[h] - mn);
            m[h] = mn;
        }
    }
    if (lane == 0) {
        #pragma unroll
        for (int h = 0; h < 4; h++) { wm[warp][h] = m[h]; wd[warp][h] = den[h]; }
    }
    __syncthreads();
    if (tid < 4) {
        int h = tid;
        float M_ = -1e30f;
        #pragma unroll
        for (int w = 0; w < 4; w++) M_ = fmaxf(M_, wm[w][h]);
        float D = 0.f;
        #pragma unroll
        for (int w = 0; w < 4; w++) D += wd[w][h] * __expf(wm[w][h] - M_);
        fm[h] = M_;
        fd[h] = D;
    }
    __syncthreads();

    int c0 = tid, c1 = tid + 128;
    int h0 = c0 >> 6, h1 = c1 >> 6;
    float rm0 = fm[h0], rm1 = fm[h1];
    float rd0 = 1.0f / fd[h0], rd1 = 1.0f / fd[h1];
    float acc0 = 0.f, acc1 = 0.f;
    for (int j = 0; j < deg; j++) {
        int eid = g_perm[rs + j];
        int s = src[eid];
        float p0 = __expf(g_sim[(size_t)(rs + j) * 4 + h0] - rm0) * rd0;
        float p1 = __expf(g_sim[(size_t)(rs + j) * 4 + h1] - rm1) * rd1;
        const float* vp = g_kv + (size_t)s * (2 * DIMC) + DIMC;
        const __nv_bfloat16* ep = e + (size_t)eid * 512;
        acc0 += p0 * (vp[c0] + __bfloat162float(ep[c0]));
        acc1 += p1 * (vp[c1] + __bfloat162float(ep[c1]));
    }
    g_agg[(size_t)node * DIMC + c0] = acc0;
    g_agg[(size_t)node * DIMC + c1] = acc1;
}

// ---------------- host orchestration ----------------
static inline dim3 grid_narrow(int M, int N) { return dim3(N / 128, (M + 127) / 128); }
static inline dim3 grid_wide(int M, int N)   { return dim3(N / 256, (M + 127) / 128); }

extern "C" void kernel_launch(void* const* d_in, const int* in_sizes, int n_in,
                              void* d_out, int out_size) {
    const float* x         = (const float*)d_in[0];
    const float* edge_attr = (const float*)d_in[1];
    const int*   edge_idx  = (const int*)  d_in[2];
    const float* ln1_g     = (const float*)d_in[3];
    const float* ln1_b     = (const float*)d_in[4];
    const float* Wq        = (const float*)d_in[5];
    const float* bq        = (const float*)d_in[6];
    const float* Wkv       = (const float*)d_in[7];
    const float* bkv       = (const float*)d_in[8];
    const float* We        = (const float*)d_in[9];
    const float* be        = (const float*)d_in[10];
    const float* Wo        = (const float*)d_in[11];
    const float* bo        = (const float*)d_in[12];
    const float* gate_attn = (const float*)d_in[13];
    const float* ln2_g     = (const float*)d_in[14];
    const float* ln2_b     = (const float*)d_in[15];
    const float* Wff1      = (const float*)d_in[16];
    const float* bff1      = (const float*)d_in[17];
    const float* Wff2      = (const float*)d_in[18];
    const float* bff2      = (const float*)d_in[19];
    const float* gate_ff   = (const float*)d_in[20];
    const float* Wproj     = (const float*)d_in[21];
    const float* bproj     = (const float*)d_in[22];

    const int* src_arr = edge_idx;
    const int* dst_arr = edge_idx + EDGES;

    cudaFuncSetAttribute(gemm_mma<0>,  cudaFuncAttributeMaxDynamicSharedMemorySize, N_GEMM_SMEM);
    cudaFuncSetAttribute(gemm_wide<0>, cudaFuncAttributeMaxDynamicSharedMemorySize, W_GEMM_SMEM);
    cudaFuncSetAttribute(gemm_wide<1>, cudaFuncAttributeMaxDynamicSharedMemorySize, W_GEMM_SMEM);
    cudaFuncSetAttribute(gemm_wide<2>, cudaFuncAttributeMaxDynamicSharedMemorySize, W_GEMM_SMEM);

    float *p_xbuf, *p_xn, *p_q, *p_kv, *p_agg, *p_y, *p_ff;
    __nv_bfloat16 *p_e, *p_ah, *p_al, *p_eah, *p_eal, *p_wh, *p_wl, *p_weh, *p_wel;
    cudaGetSymbolAddress((void**)&p_xbuf, g_xbuf);
    cudaGetSymbolAddress((void**)&p_xn,   g_xn);
    cudaGetSymbolAddress((void**)&p_q,    g_q);
    cudaGetSymbolAddress((void**)&p_kv,   g_kv);
    cudaGetSymbolAddress((void**)&p_e,    g_e);
    cudaGetSymbolAddress((void**)&p_agg,  g_agg);
    cudaGetSymbolAddress((void**)&p_y,    g_y);
    cudaGetSymbolAddress((void**)&p_ff,   g_ff);
    cudaGetSymbolAddress((void**)&p_ah,   g_act_h);
    cudaGetSymbolAddress((void**)&p_al,   g_act_l);
    cudaGetSymbolAddress((void**)&p_eah,  g_ea_h);
    cudaGetSymbolAddress((void**)&p_eal,  g_ea_l);
    cudaGetSymbolAddress((void**)&p_wh,   g_wh);
    cudaGetSymbolAddress((void**)&p_wl,   g_wl);
    cudaGetSymbolAddress((void**)&p_weh,  g_weh);
    cudaGetSymbolAddress((void**)&p_wel,  g_wel);

    dim3 tb(32, 8);
    int n4_ea = EDGES * EDIM / 4;

    // ---- front-load the edge pipeline; fused e-GEMM is launch #6 for ncu -s 5 ----
    copy_kernel<<<(NODES * DIMC + 255) / 256, 256>>>(x, p_xbuf, NODES * DIMC);                     // 1
    split_kernel<<<(n4_ea + 255) / 256, 256>>>(edge_attr, p_eah, p_eal, n4_ea);                    // 2
    tsplit_kernel<<<dim3(INNER/32, EDIM/32), tb>>>(We,                      p_weh,           p_wel,           EDIM, INNER);  // 3
    tsplit_kernel<<<dim3(INNER/32, EDIM/32), tb>>>(We + (size_t)EDIM*INNER, p_weh + 256*512, p_wel + 256*512, EDIM, INNER);  // 4
    zero_counts_kernel<<<(NODES + 255) / 256, 256>>>();                                            // 5
    // fused e-GEMM: both layers, N=512, bf16 out; col-CTA pairs share A via L2
    gemm_wide<2><<<grid_wide(EDGES, 512), 256, W_GEMM_SMEM>>>(
        p_eah, p_eal, p_weh, p_wel, be, (void*)p_e, EDGES, 512, EDIM);                             // 6

    // CSR of incoming edges
    count_kernel<<<(EDGES + 255) / 256, 256>>>(dst_arr);
    scan_kernel<<<1, 1024>>>();
    cursor_init_kernel<<<(NODES + 255) / 256, 256>>>();
    scatter_kernel<<<(EDGES + 255) / 256, 256>>>(dst_arr);

    // remaining weight transposes
    for (int d = 0; d < DEPTH; d++) {
        size_t wb = (size_t)d * WLAYER;
        tsplit_kernel<<<dim3(INNER/32,  DIMC/32),  tb>>>(Wq   + (size_t)d*DIMC*INNER,   p_wh + wb + WOFF_Q,  p_wl + wb + WOFF_Q,  DIMC,  INNER);
        tsplit_kernel<<<dim3(2*INNER/32,DIMC/32),  tb>>>(Wkv  + (size_t)d*DIMC*2*INNER, p_wh + wb + WOFF_KV, p_wl + wb + WOFF_KV, DIMC,  2*INNER);
        tsplit_kernel<<<dim3(DIMC/32,   INNER/32), tb>>>(Wo   + (size_t)d*INNER*DIMC,   p_wh + wb + WOFF_O,  p_wl + wb + WOFF_O,  INNER, DIMC);
        tsplit_kernel<<<dim3(FFDIM/32,  DIMC/32),  tb>>>(Wff1 + (size_t)d*DIMC*FFDIM,   p_wh + wb + WOFF_F1, p_wl + wb + WOFF_F1, DIMC,  FFDIM);
        tsplit_kernel<<<dim3(DIMC/32,   FFDIM/32), tb>>>(Wff2 + (size_t)d*FFDIM*DIMC,   p_wh + wb + WOFF_F2, p_wl + wb + WOFF_F2, FFDIM, DIMC);
    }
    tsplit_kernel<<<dim3(OUTC/32, DIMC/32), tb>>>(Wproj, p_wh + WOFF_P, p_wl + WOFF_P, DIMC, OUTC);

    int warps_rows_blocks = (NODES + 7) / 8;
    int n4_xn = NODES * DIMC / 4;
    int n4_ff = NODES * FFDIM / 4;

    for (int d = 0; d < DEPTH; d++) {
        size_t wb = (size_t)d * WLAYER;
        // pre-norm + split
        ln_kernel<<<warps_rows_blocks, 256>>>(p_xbuf, ln1_g + d * DIMC, ln1_b + d * DIMC, p_xn);
        split_kernel<<<(n4_xn + 255) / 256, 256>>>(p_xn, p_ah, p_al, n4_xn);
        // projections
        gemm_wide<0><<<grid_wide(NODES, INNER), 256, W_GEMM_SMEM>>>(
            p_ah, p_al, p_wh + wb + WOFF_Q, p_wl + wb + WOFF_Q, bq + d * INNER, (void*)p_q, NODES, INNER, DIMC);
        gemm_wide<0><<<grid_wide(NODES, 2 * INNER), 256, W_GEMM_SMEM>>>(
            p_ah, p_al, p_wh + wb + WOFF_KV, p_wl + wb + WOFF_KV, bkv + d * 2 * INNER, (void*)p_kv, NODES, 2 * INNER, DIMC);
        // sparse attention (e for this layer: bf16, stride 512, column offset d*256)
        attn_kernel<<<NODES, 128>>>(src_arr, p_e + (size_t)d * 256);
        // output projection + gated residual
        split_kernel<<<(n4_xn + 255) / 256, 256>>>(p_agg, p_ah, p_al, n4_xn);
        gemm_mma<0><<<grid_narrow(NODES, DIMC), 256, N_GEMM_SMEM>>>(
            p_ah, p_al, p_wh + wb + WOFF_O, p_wl + wb + WOFF_O, bo + d * DIMC, p_y, NODES, DIMC, INNER);
        gated_residual_kernel<<<warps_rows_blocks, 256>>>(p_y, p_xbuf, gate_attn + (size_t)d * 3 * DIMC);
        // feedforward
        ln_kernel<<<warps_rows_blocks, 256>>>(p_xbuf, ln2_g + d * DIMC, ln2_b + d * DIMC, p_xn);
        split_kernel<<<(n4_xn + 255) / 256, 256>>>(p_xn, p_ah, p_al, n4_xn);
        gemm_wide<1><<<grid_wide(NODES, FFDIM), 256, W_GEMM_SMEM>>>(
            p_ah, p_al, p_wh + wb + WOFF_F1, p_wl + wb + WOFF_F1, bff1 + d * FFDIM, (void*)p_ff, NODES, FFDIM, DIMC);
        split_kernel<<<(n4_ff + 255) / 256, 256>>>(p_ff, p_ah, p_al, n4_ff);
        gemm_wide<0><<<grid_wide(NODES, DIMC), 256, W_GEMM_SMEM>>>(
            p_ah, p_al, p_wh + wb + WOFF_F2, p_wl + wb + WOFF_F2, bff2 + d * DIMC, (void*)p_y, NODES, DIMC, FFDIM);
        gated_residual_kernel<<<warps_rows_blocks, 256>>>(p_y, p_xbuf, gate_ff + (size_t)d * 3 * DIMC);
    }

    // final projection
    split_kernel<<<(n4_xn + 255) / 256, 256>>>(p_xbuf, p_ah, p_al, n4_xn);
    gemm_mma<0><<<grid_narrow(NODES, OUTC), 256, N_GEMM_SMEM>>>(
        p_ah, p_al, p_wh + WOFF_P, p_wl + WOFF_P, bproj, (float*)d_out, NODES, OUTC, DIMC);
}